// round 1
// baseline (speedup 1.0000x reference)
#include <cuda_runtime.h>

#define T_   12
#define M_   32
#define H_   64
#define DIN_ 2
#define P_   12
#define BN_TOT 131072
#define NPRED  (BN_TOT * P_)

// ---------------- device scratch (no allocations allowed) ----------------
__device__ __align__(16) float g_Wrx[T_ * H_ * DIN_];   // 1536
__device__ __align__(16) float g_Wrh[T_ * H_ * H_];     // 49152
__device__ __align__(16) float g_Wzx[T_ * H_ * DIN_];
__device__ __align__(16) float g_Wzh[T_ * H_ * H_];
__device__ __align__(16) float g_Wcx[T_ * H_ * DIN_];
__device__ __align__(16) float g_Wch[T_ * H_ * H_];
__device__ float g_brx[T_ * H_];
__device__ float g_brh[T_ * H_];
__device__ float g_bzx[T_ * H_];
__device__ float g_bzh[T_ * H_];
__device__ float g_bcx[T_ * H_];
__device__ float g_bch[T_ * H_];

// ---------------- helpers ----------------
__device__ __forceinline__ unsigned long long fma2(unsigned long long a,
                                                   unsigned long long b,
                                                   unsigned long long c) {
    unsigned long long d;
    asm("fma.rn.f32x2 %0, %1, %2, %3;" : "=l"(d) : "l"(a), "l"(b), "l"(c));
    return d;
}
__device__ __forceinline__ float2 unpack2(unsigned long long v) {
    float2 r;
    asm("mov.b64 {%0, %1}, %2;" : "=f"(r.x), "=f"(r.y) : "l"(v));
    return r;
}
__device__ __forceinline__ unsigned long long pack2(float x, float y) {
    unsigned long long v;
    asm("mov.b64 %0, {%1, %2};" : "=l"(v) : "f"(x), "f"(y));
    return v;
}
__device__ __forceinline__ float sigf(float x) {
    return __fdividef(1.0f, 1.0f + __expf(-x));
}
__device__ __forceinline__ float tanhf_fast(float x) {
    float e = __expf(2.0f * x);                // robust at both tails
    return 1.0f - __fdividef(2.0f, e + 1.0f);
}

// ---------------- precompute meta-generated weights ----------------
__device__ __forceinline__ void meta_elem(float* out, int e, int logR,
                                          const float* __restrict__ vec,
                                          const float* __restrict__ Wl,
                                          const float* __restrict__ bl) {
    int t = e >> logR;
    int r = e & ((1 << logR) - 1);
    const float* wrow = Wl + r * M_;
    const float* vrow = vec + t * M_;
    float s = bl[r];
#pragma unroll
    for (int m = 0; m < M_; m++) s = fmaf(vrow[m], wrow[m], s);
    out[e] = s;
}

__global__ void precompute_kernel(
    const float* __restrict__ wz, const float* __restrict__ bz,
    const float* __restrict__ Wl_rx, const float* __restrict__ bl_rx,
    const float* __restrict__ Wb_rx, const float* __restrict__ bb_rx,
    const float* __restrict__ Wl_rh, const float* __restrict__ bl_rh,
    const float* __restrict__ Wb_rh, const float* __restrict__ bb_rh,
    const float* __restrict__ Wl_zx, const float* __restrict__ bl_zx,
    const float* __restrict__ Wb_zx, const float* __restrict__ bb_zx,
    const float* __restrict__ Wl_zh, const float* __restrict__ bl_zh,
    const float* __restrict__ Wb_zh, const float* __restrict__ bb_zh,
    const float* __restrict__ Wl_cx, const float* __restrict__ bl_cx,
    const float* __restrict__ Wb_cx, const float* __restrict__ bb_cx,
    const float* __restrict__ Wl_ch, const float* __restrict__ bl_ch,
    const float* __restrict__ Wb_ch, const float* __restrict__ bb_ch)
{
    int idx = blockIdx.x * blockDim.x + threadIdx.x;
    if (idx < 50688) {
        if (idx < 1536) meta_elem(g_Wrx, idx, 7, wz, Wl_rx, bl_rx);
        else            meta_elem(g_Wrh, idx - 1536, 12, wz, Wl_rh, bl_rh);
    } else if (idx < 101376) {
        if (idx < 52224) meta_elem(g_Wzx, idx - 50688, 7, wz, Wl_zx, bl_zx);
        else             meta_elem(g_Wzh, idx - 52224, 12, wz, Wl_zh, bl_zh);
    } else if (idx < 152064) {
        if (idx < 102912) meta_elem(g_Wcx, idx - 101376, 7, wz, Wl_cx, bl_cx);
        else              meta_elem(g_Wch, idx - 102912, 12, wz, Wl_ch, bl_ch);
    } else if (idx < 156672) {
        int e = idx - 152064;
        int which = e / 768;
        e -= which * 768;
        switch (which) {
            case 0: meta_elem(g_brx, e, 6, bz, Wb_rx, bb_rx); break;
            case 1: meta_elem(g_brh, e, 6, bz, Wb_rh, bb_rh); break;
            case 2: meta_elem(g_bzx, e, 6, bz, Wb_zx, bb_zx); break;
            case 3: meta_elem(g_bzh, e, 6, bz, Wb_zh, bb_zh); break;
            case 4: meta_elem(g_bcx, e, 6, bz, Wb_cx, bb_cx); break;
            case 5: meta_elem(g_bch, e, 6, bz, Wb_ch, bb_ch); break;
        }
    }
}

// ---------------- GRU main kernel ----------------
// smem layout (floats):
//   sW     [0, 12288)      gate weights Wrh|Wzh|Wch for current step
//   sStage [12288, 20480)  h staging, transposed [j][tid] (column-private)
//   sx     [20480, 23680)  x per seq, padded rows of 25
//   sWx    [23680, 24064)  Wrx|Wzx|Wcx for step (i*2+d)
//   sb     [24064, 24320)  br | bz | bcx | bch
//   sWo    [24320, 24384)
//   sWp    [24384, 24528)
//   sbp    [24528, 24544)
//   sSeq   [24544, 26080)  relu(out_t), [t][tid]
#define SMEM_FLOATS 26080
#define SMEM_BYTES  (SMEM_FLOATS * 4)

__global__ void __launch_bounds__(128, 2)
gru_kernel(const float* __restrict__ x,
           const float* __restrict__ Wo, const float* __restrict__ bo,
           const float* __restrict__ Wp, const float* __restrict__ bp,
           float* __restrict__ out, int dup)
{
    extern __shared__ float smem[];
    float* sW     = smem;
    float* sStage = smem + 12288;
    float* sx     = smem + 20480;
    float* sWx    = smem + 23680;
    float* sb     = smem + 24064;
    float* sWo    = smem + 24320;
    float* sWp    = smem + 24384;
    float* sbp    = smem + 24528;
    float* sSeq   = smem + 24544;

    const int tid = threadIdx.x;
    const int bn0 = blockIdx.x * 128;

    // ---- stage constants ----
    if (tid < 64) sWo[tid] = Wo[tid];
    if (tid < P_) sbp[tid] = bp[tid];
    for (int k = tid; k < P_ * T_; k += 128) sWp[k] = Wp[k];

    // ---- stage x: each thread copies its own 24 floats into padded row ----
    {
        const float4* gx = reinterpret_cast<const float4*>(x) + (size_t)(bn0 + tid) * 6;
#pragma unroll
        for (int u = 0; u < 6; u++) {
            float4 v = gx[u];
            sx[tid * 25 + 4 * u + 0] = v.x;
            sx[tid * 25 + 4 * u + 1] = v.y;
            sx[tid * 25 + 4 * u + 2] = v.z;
            sx[tid * 25 + 4 * u + 3] = v.w;
        }
    }

    // ---- init h (regs, K-packed f32x2) and private staging column ----
    unsigned long long h2[32];
#pragma unroll
    for (int k = 0; k < 32; k++) h2[k] = 0ull;
#pragma unroll
    for (int j = 0; j < 64; j++) sStage[j * 128 + tid] = 0.0f;

    const float bo0 = __ldg(bo);

    for (int t = 0; t < T_; t++) {
        __syncthreads();  // previous step's sW reads done
        {
            const float4* wr4 = reinterpret_cast<const float4*>(g_Wrh + t * 4096);
            const float4* wz4 = reinterpret_cast<const float4*>(g_Wzh + t * 4096);
            const float4* wc4 = reinterpret_cast<const float4*>(g_Wch + t * 4096);
            float4* dW = reinterpret_cast<float4*>(sW);
#pragma unroll
            for (int k = 0; k < 8; k++) {
                dW[k * 128 + tid]        = wr4[k * 128 + tid];
                dW[1024 + k * 128 + tid] = wz4[k * 128 + tid];
                dW[2048 + k * 128 + tid] = wc4[k * 128 + tid];
            }
            sWx[tid]       = g_Wrx[t * 128 + tid];
            sWx[128 + tid] = g_Wzx[t * 128 + tid];
            sWx[256 + tid] = g_Wcx[t * 128 + tid];
            if (tid < 64) {
                sb[tid]        = g_brx[t * 64 + tid] + g_brh[t * 64 + tid];
                sb[64 + tid]   = g_bzx[t * 64 + tid] + g_bzh[t * 64 + tid];
                sb[128 + tid]  = g_bcx[t * 64 + tid];
                sb[192 + tid]  = g_bch[t * 64 + tid];
            }
        }
        __syncthreads();

        const float x0 = sx[tid * 25 + 2 * t];
        const float x1 = sx[tid * 25 + 2 * t + 1];
        float o = bo0;

#pragma unroll 4
        for (int i = 0; i < 64; i++) {
            unsigned long long ar = 0ull, az = 0ull, ac = 0ull;
            const ulonglong2* wr = reinterpret_cast<const ulonglong2*>(sW + i * 64);
            const ulonglong2* wq = reinterpret_cast<const ulonglong2*>(sW + 4096 + i * 64);
            const ulonglong2* wc = reinterpret_cast<const ulonglong2*>(sW + 8192 + i * 64);
#pragma unroll
            for (int q = 0; q < 16; q++) {
                ulonglong2 a = wr[q];
                ulonglong2 b = wq[q];
                ulonglong2 c = wc[q];
                ar = fma2(h2[2 * q],     a.x, ar);
                az = fma2(h2[2 * q],     b.x, az);
                ac = fma2(h2[2 * q],     c.x, ac);
                ar = fma2(h2[2 * q + 1], a.y, ar);
                az = fma2(h2[2 * q + 1], b.y, az);
                ac = fma2(h2[2 * q + 1], c.y, ac);
            }
            float2 vr = unpack2(ar), vz = unpack2(az), vc = unpack2(ac);
            float dr = vr.x + vr.y;
            float dz = vz.x + vz.y;
            float dc = vc.x + vc.y;

            float r  = sigf(dr + x0 * sWx[2 * i]       + x1 * sWx[2 * i + 1]       + sb[i]);
            float zg = sigf(dz + x0 * sWx[128 + 2 * i] + x1 * sWx[128 + 2 * i + 1] + sb[64 + i]);
            float cc = tanhf_fast(x0 * sWx[256 + 2 * i] + x1 * sWx[256 + 2 * i + 1]
                                  + sb[128 + i] + r * (dc + sb[192 + i]));
            float hold = sStage[i * 128 + tid];
            float hn = (1.0f - zg) * cc + zg * hold;
            sStage[i * 128 + tid] = hn;           // column-private, no sync needed
            o = fmaf(hn, sWo[i], o);
        }
        sSeq[t * 128 + tid] = fmaxf(o, 0.0f);

        // repack new h into f32x2 registers
#pragma unroll
        for (int k = 0; k < 32; k++) {
            h2[k] = pack2(sStage[(2 * k) * 128 + tid],
                          sStage[(2 * k + 1) * 128 + tid]);
        }
    }

    // ---- predictor: pred[p] = sum_t seq[t] * Wp[p,t] + bp[p] ----
    const size_t base = (size_t)(bn0 + tid) * P_;
#pragma unroll
    for (int p = 0; p < P_; p++) {
        float acc = sbp[p];
#pragma unroll
        for (int t = 0; t < T_; t++)
            acc = fmaf(sSeq[t * 128 + tid], sWp[p * T_ + t], acc);
        out[base + p] = acc;
        if (dup) out[NPRED + base + p] = acc;
    }
}

// ---------------- launch ----------------
extern "C" void kernel_launch(void* const* d_in, const int* in_sizes, int n_in,
                              void* d_out, int out_size) {
    const float* x  = (const float*)d_in[0];
    const float* wz = (const float*)d_in[2];
    const float* bz = (const float*)d_in[3];
    const float* Wl_rx = (const float*)d_in[4];
    const float* bl_rx = (const float*)d_in[5];
    const float* Wb_rx = (const float*)d_in[6];
    const float* bb_rx = (const float*)d_in[7];
    const float* Wl_rh = (const float*)d_in[8];
    const float* bl_rh = (const float*)d_in[9];
    const float* Wb_rh = (const float*)d_in[10];
    const float* bb_rh = (const float*)d_in[11];
    const float* Wl_zx = (const float*)d_in[12];
    const float* bl_zx = (const float*)d_in[13];
    const float* Wb_zx = (const float*)d_in[14];
    const float* bb_zx = (const float*)d_in[15];
    const float* Wl_zh = (const float*)d_in[16];
    const float* bl_zh = (const float*)d_in[17];
    const float* Wb_zh = (const float*)d_in[18];
    const float* bb_zh = (const float*)d_in[19];
    const float* Wl_cx = (const float*)d_in[20];
    const float* bl_cx = (const float*)d_in[21];
    const float* Wb_cx = (const float*)d_in[22];
    const float* bb_cx = (const float*)d_in[23];
    const float* Wl_ch = (const float*)d_in[24];
    const float* bl_ch = (const float*)d_in[25];
    const float* Wb_ch = (const float*)d_in[26];
    const float* bb_ch = (const float*)d_in[27];
    const float* Wo = (const float*)d_in[28];
    const float* bo = (const float*)d_in[29];
    const float* Wp = (const float*)d_in[30];
    const float* bp = (const float*)d_in[31];
    float* out = (float*)d_out;

    precompute_kernel<<<612, 256>>>(
        wz, bz,
        Wl_rx, bl_rx, Wb_rx, bb_rx,
        Wl_rh, bl_rh, Wb_rh, bb_rh,
        Wl_zx, bl_zx, Wb_zx, bb_zx,
        Wl_zh, bl_zh, Wb_zh, bb_zh,
        Wl_cx, bl_cx, Wb_cx, bb_cx,
        Wl_ch, bl_ch, Wb_ch, bb_ch);

    int dup = (out_size >= 2 * NPRED) ? 1 : 0;
    cudaFuncSetAttribute(gru_kernel,
                         cudaFuncAttributeMaxDynamicSharedMemorySize, SMEM_BYTES);
    gru_kernel<<<1024, 128, SMEM_BYTES>>>(x, Wo, bo, Wp, bp, out, dup);
}

// round 3
// speedup vs baseline: 1.0011x; 1.0011x over previous
#include <cuda_runtime.h>

#define T_   12
#define M_   32
#define H_   64
#define DIN_ 2
#define P_   12
#define BN_TOT 131072
#define NPRED  (BN_TOT * P_)

// ---------------- device scratch (no allocations allowed) ----------------
__device__ __align__(16) float g_Wrx[T_ * H_ * DIN_];   // 1536
__device__ __align__(16) float g_Wrh[T_ * H_ * H_];     // 49152
__device__ __align__(16) float g_Wzx[T_ * H_ * DIN_];
__device__ __align__(16) float g_Wzh[T_ * H_ * H_];
__device__ __align__(16) float g_Wcx[T_ * H_ * DIN_];
__device__ __align__(16) float g_Wch[T_ * H_ * H_];
__device__ float g_brx[T_ * H_];
__device__ float g_brh[T_ * H_];
__device__ float g_bzx[T_ * H_];
__device__ float g_bzh[T_ * H_];
__device__ float g_bcx[T_ * H_];
__device__ float g_bch[T_ * H_];

// ---------------- helpers ----------------
__device__ __forceinline__ unsigned long long fma2(unsigned long long a,
                                                   unsigned long long b,
                                                   unsigned long long c) {
    unsigned long long d;
    asm("fma.rn.f32x2 %0, %1, %2, %3;" : "=l"(d) : "l"(a), "l"(b), "l"(c));
    return d;
}
__device__ __forceinline__ float2 unpack2(unsigned long long v) {
    float2 r;
    asm("mov.b64 {%0, %1}, %2;" : "=f"(r.x), "=f"(r.y) : "l"(v));
    return r;
}
__device__ __forceinline__ unsigned long long pack2(float x, float y) {
    unsigned long long v;
    asm("mov.b64 %0, {%1, %2};" : "=l"(v) : "f"(x), "f"(y));
    return v;
}
__device__ __forceinline__ float sigf(float x) {
    return __fdividef(1.0f, 1.0f + __expf(-x));
}
__device__ __forceinline__ float tanhf_fast(float x) {
    float e = __expf(2.0f * x);                // robust at both tails
    return 1.0f - __fdividef(2.0f, e + 1.0f);
}

// ---------------- precompute meta-generated weights ----------------
__device__ __forceinline__ void meta_elem(float* out, int e, int logR,
                                          const float* __restrict__ vec,
                                          const float* __restrict__ Wl,
                                          const float* __restrict__ bl) {
    int t = e >> logR;
    int r = e & ((1 << logR) - 1);
    const float* wrow = Wl + r * M_;
    const float* vrow = vec + t * M_;
    float s = bl[r];
#pragma unroll
    for (int m = 0; m < M_; m++) s = fmaf(vrow[m], wrow[m], s);
    out[e] = s;
}

__global__ void precompute_kernel(
    const float* __restrict__ wz, const float* __restrict__ bz,
    const float* __restrict__ Wl_rx, const float* __restrict__ bl_rx,
    const float* __restrict__ Wb_rx, const float* __restrict__ bb_rx,
    const float* __restrict__ Wl_rh, const float* __restrict__ bl_rh,
    const float* __restrict__ Wb_rh, const float* __restrict__ bb_rh,
    const float* __restrict__ Wl_zx, const float* __restrict__ bl_zx,
    const float* __restrict__ Wb_zx, const float* __restrict__ bb_zx,
    const float* __restrict__ Wl_zh, const float* __restrict__ bl_zh,
    const float* __restrict__ Wb_zh, const float* __restrict__ bb_zh,
    const float* __restrict__ Wl_cx, const float* __restrict__ bl_cx,
    const float* __restrict__ Wb_cx, const float* __restrict__ bb_cx,
    const float* __restrict__ Wl_ch, const float* __restrict__ bl_ch,
    const float* __restrict__ Wb_ch, const float* __restrict__ bb_ch)
{
    int idx = blockIdx.x * blockDim.x + threadIdx.x;
    if (idx < 50688) {
        if (idx < 1536) meta_elem(g_Wrx, idx, 7, wz, Wl_rx, bl_rx);
        else            meta_elem(g_Wrh, idx - 1536, 12, wz, Wl_rh, bl_rh);
    } else if (idx < 101376) {
        if (idx < 52224) meta_elem(g_Wzx, idx - 50688, 7, wz, Wl_zx, bl_zx);
        else             meta_elem(g_Wzh, idx - 52224, 12, wz, Wl_zh, bl_zh);
    } else if (idx < 152064) {
        if (idx < 102912) meta_elem(g_Wcx, idx - 101376, 7, wz, Wl_cx, bl_cx);
        else              meta_elem(g_Wch, idx - 102912, 12, wz, Wl_ch, bl_ch);
    } else if (idx < 156672) {
        int e = idx - 152064;
        int which = e / 768;
        e -= which * 768;
        switch (which) {
            case 0: meta_elem(g_brx, e, 6, bz, Wb_rx, bb_rx); break;
            case 1: meta_elem(g_brh, e, 6, bz, Wb_rh, bb_rh); break;
            case 2: meta_elem(g_bzx, e, 6, bz, Wb_zx, bb_zx); break;
            case 3: meta_elem(g_bzh, e, 6, bz, Wb_zh, bb_zh); break;
            case 4: meta_elem(g_bcx, e, 6, bz, Wb_cx, bb_cx); break;
            case 5: meta_elem(g_bch, e, 6, bz, Wb_ch, bb_ch); break;
        }
    }
}

// ---------------- GRU main kernel ----------------
// smem layout (floats):
//   sW     [0, 12288)      gate weights Wrh|Wzh|Wch for current step
//   sStage [12288, 20480)  h staging, transposed [j][tid] (column-private)
//   sx     [20480, 23680)  x per seq, padded rows of 25
//   sWx    [23680, 24064)  Wrx|Wzx|Wcx for step (i*2+d)
//   sb     [24064, 24320)  br | bz | bcx | bch
//   sWo    [24320, 24384)
//   sWp    [24384, 24528)
//   sbp    [24528, 24544)
//   sSeq   [24544, 26080)  relu(out_t), [t][tid]
#define SMEM_FLOATS 26080
#define SMEM_BYTES  (SMEM_FLOATS * 4)

__global__ void __launch_bounds__(128, 2)
gru_kernel(const float* __restrict__ x,
           const float* __restrict__ Wo, const float* __restrict__ bo,
           const float* __restrict__ Wp, const float* __restrict__ bp,
           float* __restrict__ out, int dup)
{
    extern __shared__ float smem[];
    float* sW     = smem;
    float* sStage = smem + 12288;
    float* sx     = smem + 20480;
    float* sWx    = smem + 23680;
    float* sb     = smem + 24064;
    float* sWo    = smem + 24320;
    float* sWp    = smem + 24384;
    float* sbp    = smem + 24528;
    float* sSeq   = smem + 24544;

    const int tid = threadIdx.x;
    const int bn0 = blockIdx.x * 128;

    // ---- stage constants ----
    if (tid < 64) sWo[tid] = Wo[tid];
    if (tid < P_) sbp[tid] = bp[tid];
    for (int k = tid; k < P_ * T_; k += 128) sWp[k] = Wp[k];

    // ---- stage x: each thread copies its own 24 floats into padded row ----
    {
        const float4* gx = reinterpret_cast<const float4*>(x) + (size_t)(bn0 + tid) * 6;
#pragma unroll
        for (int u = 0; u < 6; u++) {
            float4 v = gx[u];
            sx[tid * 25 + 4 * u + 0] = v.x;
            sx[tid * 25 + 4 * u + 1] = v.y;
            sx[tid * 25 + 4 * u + 2] = v.z;
            sx[tid * 25 + 4 * u + 3] = v.w;
        }
    }

    // ---- init h (regs, K-packed f32x2) and private staging column ----
    unsigned long long h2[32];
#pragma unroll
    for (int k = 0; k < 32; k++) h2[k] = 0ull;
#pragma unroll
    for (int j = 0; j < 64; j++) sStage[j * 128 + tid] = 0.0f;

    const float bo0 = __ldg(bo);

    for (int t = 0; t < T_; t++) {
        __syncthreads();  // previous step's sW reads done
        {
            const float4* wr4 = reinterpret_cast<const float4*>(g_Wrh + t * 4096);
            const float4* wz4 = reinterpret_cast<const float4*>(g_Wzh + t * 4096);
            const float4* wc4 = reinterpret_cast<const float4*>(g_Wch + t * 4096);
            float4* dW = reinterpret_cast<float4*>(sW);
#pragma unroll
            for (int k = 0; k < 8; k++) {
                dW[k * 128 + tid]        = wr4[k * 128 + tid];
                dW[1024 + k * 128 + tid] = wz4[k * 128 + tid];
                dW[2048 + k * 128 + tid] = wc4[k * 128 + tid];
            }
            sWx[tid]       = g_Wrx[t * 128 + tid];
            sWx[128 + tid] = g_Wzx[t * 128 + tid];
            sWx[256 + tid] = g_Wcx[t * 128 + tid];
            if (tid < 64) {
                sb[tid]        = g_brx[t * 64 + tid] + g_brh[t * 64 + tid];
                sb[64 + tid]   = g_bzx[t * 64 + tid] + g_bzh[t * 64 + tid];
                sb[128 + tid]  = g_bcx[t * 64 + tid];
                sb[192 + tid]  = g_bch[t * 64 + tid];
            }
        }
        __syncthreads();

        const float x0 = sx[tid * 25 + 2 * t];
        const float x1 = sx[tid * 25 + 2 * t + 1];
        float o = bo0;

#pragma unroll 4
        for (int i = 0; i < 64; i++) {
            unsigned long long ar = 0ull, az = 0ull, ac = 0ull;
            const ulonglong2* wr = reinterpret_cast<const ulonglong2*>(sW + i * 64);
            const ulonglong2* wq = reinterpret_cast<const ulonglong2*>(sW + 4096 + i * 64);
            const ulonglong2* wc = reinterpret_cast<const ulonglong2*>(sW + 8192 + i * 64);
#pragma unroll
            for (int q = 0; q < 16; q++) {
                ulonglong2 a = wr[q];
                ulonglong2 b = wq[q];
                ulonglong2 c = wc[q];
                ar = fma2(h2[2 * q],     a.x, ar);
                az = fma2(h2[2 * q],     b.x, az);
                ac = fma2(h2[2 * q],     c.x, ac);
                ar = fma2(h2[2 * q + 1], a.y, ar);
                az = fma2(h2[2 * q + 1], b.y, az);
                ac = fma2(h2[2 * q + 1], c.y, ac);
            }
            float2 vr = unpack2(ar), vz = unpack2(az), vc = unpack2(ac);
            float dr = vr.x + vr.y;
            float dz = vz.x + vz.y;
            float dc = vc.x + vc.y;

            float r  = sigf(dr + x0 * sWx[2 * i]       + x1 * sWx[2 * i + 1]       + sb[i]);
            float zg = sigf(dz + x0 * sWx[128 + 2 * i] + x1 * sWx[128 + 2 * i + 1] + sb[64 + i]);
            float cc = tanhf_fast(x0 * sWx[256 + 2 * i] + x1 * sWx[256 + 2 * i + 1]
                                  + sb[128 + i] + r * (dc + sb[192 + i]));
            float hold = sStage[i * 128 + tid];
            float hn = (1.0f - zg) * cc + zg * hold;
            sStage[i * 128 + tid] = hn;           // column-private, no sync needed
            o = fmaf(hn, sWo[i], o);
        }
        sSeq[t * 128 + tid] = fmaxf(o, 0.0f);

        // repack new h into f32x2 registers
#pragma unroll
        for (int k = 0; k < 32; k++) {
            h2[k] = pack2(sStage[(2 * k) * 128 + tid],
                          sStage[(2 * k + 1) * 128 + tid]);
        }
    }

    // ---- predictor: pred[p] = sum_t seq[t] * Wp[p,t] + bp[p] ----
    const size_t base = (size_t)(bn0 + tid) * P_;
#pragma unroll
    for (int p = 0; p < P_; p++) {
        float acc = sbp[p];
#pragma unroll
        for (int t = 0; t < T_; t++)
            acc = fmaf(sSeq[t * 128 + tid], sWp[p * T_ + t], acc);
        out[base + p] = acc;
        if (dup) out[NPRED + base + p] = acc;
    }
}

// ---------------- launch ----------------
extern "C" void kernel_launch(void* const* d_in, const int* in_sizes, int n_in,
                              void* d_out, int out_size) {
    const float* x  = (const float*)d_in[0];
    const float* wz = (const float*)d_in[2];
    const float* bz = (const float*)d_in[3];
    const float* Wl_rx = (const float*)d_in[4];
    const float* bl_rx = (const float*)d_in[5];
    const float* Wb_rx = (const float*)d_in[6];
    const float* bb_rx = (const float*)d_in[7];
    const float* Wl_rh = (const float*)d_in[8];
    const float* bl_rh = (const float*)d_in[9];
    const float* Wb_rh = (const float*)d_in[10];
    const float* bb_rh = (const float*)d_in[11];
    const float* Wl_zx = (const float*)d_in[12];
    const float* bl_zx = (const float*)d_in[13];
    const float* Wb_zx = (const float*)d_in[14];
    const float* bb_zx = (const float*)d_in[15];
    const float* Wl_zh = (const float*)d_in[16];
    const float* bl_zh = (const float*)d_in[17];
    const float* Wb_zh = (const float*)d_in[18];
    const float* bb_zh = (const float*)d_in[19];
    const float* Wl_cx = (const float*)d_in[20];
    const float* bl_cx = (const float*)d_in[21];
    const float* Wb_cx = (const float*)d_in[22];
    const float* bb_cx = (const float*)d_in[23];
    const float* Wl_ch = (const float*)d_in[24];
    const float* bl_ch = (const float*)d_in[25];
    const float* Wb_ch = (const float*)d_in[26];
    const float* bb_ch = (const float*)d_in[27];
    const float* Wo = (const float*)d_in[28];
    const float* bo = (const float*)d_in[29];
    const float* Wp = (const float*)d_in[30];
    const float* bp = (const float*)d_in[31];
    float* out = (float*)d_out;

    precompute_kernel<<<612, 256>>>(
        wz, bz,
        Wl_rx, bl_rx, Wb_rx, bb_rx,
        Wl_rh, bl_rh, Wb_rh, bb_rh,
        Wl_zx, bl_zx, Wb_zx, bb_zx,
        Wl_zh, bl_zh, Wb_zh, bb_zh,
        Wl_cx, bl_cx, Wb_cx, bb_cx,
        Wl_ch, bl_ch, Wb_ch, bb_ch);

    int dup = (out_size >= 2 * NPRED) ? 1 : 0;
    cudaFuncSetAttribute(gru_kernel,
                         cudaFuncAttributeMaxDynamicSharedMemorySize, SMEM_BYTES);
    gru_kernel<<<1024, 128, SMEM_BYTES>>>(x, Wo, bo, Wp, bp, out, dup);
}

// round 4
// speedup vs baseline: 1.2529x; 1.2516x over previous
#include <cuda_runtime.h>

#define T_   12
#define M_   32
#define H_   64
#define P_   12
#define BN_TOT 131072
#define NPRED  (BN_TOT * P_)

__device__ __align__(16) float g_Wrx[T_ * 128];
__device__ __align__(16) float g_Wrh[T_ * 4096];
__device__ __align__(16) float g_Wzx[T_ * 128];
__device__ __align__(16) float g_Wzh[T_ * 4096];
__device__ __align__(16) float g_Wcx[T_ * 128];
__device__ __align__(16) float g_Wch[T_ * 4096];
__device__ float g_brx[T_ * 64];
__device__ float g_brh[T_ * 64];
__device__ float g_bzx[T_ * 64];
__device__ float g_bzh[T_ * 64];
__device__ float g_bcx[T_ * 64];
__device__ float g_bch[T_ * 64];

typedef unsigned long long u64;

__device__ __forceinline__ u64 fma2(u64 a, u64 b, u64 c) {
    u64 d;
    asm("fma.rn.f32x2 %0, %1, %2, %3;" : "=l"(d) : "l"(a), "l"(b), "l"(c));
    return d;
}
__device__ __forceinline__ float2 unpack2(u64 v) {
    float2 r;
    asm("mov.b64 {%0, %1}, %2;" : "=f"(r.x), "=f"(r.y) : "l"(v));
    return r;
}
__device__ __forceinline__ u64 pack2(float x, float y) {
    u64 v;
    asm("mov.b64 %0, {%1, %2};" : "=l"(v) : "f"(x), "f"(y));
    return v;
}
__device__ __forceinline__ float sigf(float x) {
    return __fdividef(1.0f, 1.0f + __expf(-x));
}
__device__ __forceinline__ float tanhf_fast(float x) {
    float e = __expf(2.0f * x);
    return 1.0f - __fdividef(2.0f, e + 1.0f);
}

__device__ __forceinline__ void meta_elem(float* out, int e, int logR,
                                          const float* __restrict__ vec,
                                          const float* __restrict__ Wl,
                                          const float* __restrict__ bl) {
    int t = e >> logR;
    int r = e & ((1 << logR) - 1);
    const float* wrow = Wl + r * M_;
    const float* vrow = vec + t * M_;
    float s = bl[r];
#pragma unroll
    for (int m = 0; m < M_; m++) s = fmaf(vrow[m], wrow[m], s);
    out[e] = s;
}

__global__ void precompute_kernel(
    const float* __restrict__ wz, const float* __restrict__ bz,
    const float* __restrict__ Wl_rx, const float* __restrict__ bl_rx,
    const float* __restrict__ Wb_rx, const float* __restrict__ bb_rx,
    const float* __restrict__ Wl_rh, const float* __restrict__ bl_rh,
    const float* __restrict__ Wb_rh, const float* __restrict__ bb_rh,
    const float* __restrict__ Wl_zx, const float* __restrict__ bl_zx,
    const float* __restrict__ Wb_zx, const float* __restrict__ bb_zx,
    const float* __restrict__ Wl_zh, const float* __restrict__ bl_zh,
    const float* __restrict__ Wb_zh, const float* __restrict__ bb_zh,
    const float* __restrict__ Wl_cx, const float* __restrict__ bl_cx,
    const float* __restrict__ Wb_cx, const float* __restrict__ bb_cx,
    const float* __restrict__ Wl_ch, const float* __restrict__ bl_ch,
    const float* __restrict__ Wb_ch, const float* __restrict__ bb_ch)
{
    int idx = blockIdx.x * blockDim.x + threadIdx.x;
    if (idx < 50688) {
        if (idx < 1536) meta_elem(g_Wrx, idx, 7, wz, Wl_rx, bl_rx);
        else            meta_elem(g_Wrh, idx - 1536, 12, wz, Wl_rh, bl_rh);
    } else if (idx < 101376) {
        if (idx < 52224) meta_elem(g_Wzx, idx - 50688, 7, wz, Wl_zx, bl_zx);
        else             meta_elem(g_Wzh, idx - 52224, 12, wz, Wl_zh, bl_zh);
    } else if (idx < 152064) {
        if (idx < 102912) meta_elem(g_Wcx, idx - 101376, 7, wz, Wl_cx, bl_cx);
        else              meta_elem(g_Wch, idx - 102912, 12, wz, Wl_ch, bl_ch);
    } else if (idx < 156672) {
        int e = idx - 152064;
        int which = e / 768;
        e -= which * 768;
        switch (which) {
            case 0: meta_elem(g_brx, e, 6, bz, Wb_rx, bb_rx); break;
            case 1: meta_elem(g_brh, e, 6, bz, Wb_rh, bb_rh); break;
            case 2: meta_elem(g_bzx, e, 6, bz, Wb_zx, bb_zx); break;
            case 3: meta_elem(g_bzh, e, 6, bz, Wb_zh, bb_zh); break;
            case 4: meta_elem(g_bcx, e, 6, bz, Wb_cx, bb_cx); break;
            case 5: meta_elem(g_bch, e, 6, bz, Wb_ch, bb_ch); break;
        }
    }
}

// smem floats: sW 12288 | sx 6400 | sWx 384 | sb 256 | sWo 64 | sWp 144 | sbp 16 | sSeq 3072
#define SMEM_FLOATS 22624
#define SMEM_BYTES  (SMEM_FLOATS * 4)

__global__ void __launch_bounds__(128, 2)
gru_kernel(const float* __restrict__ x,
           const float* __restrict__ Wo, const float* __restrict__ bo,
           const float* __restrict__ Wp, const float* __restrict__ bp,
           float* __restrict__ out, int dup)
{
    extern __shared__ float smem[];
    float* sW   = smem;
    float* sx   = smem + 12288;
    float* sWx  = smem + 18688;
    float* sb   = smem + 19072;
    float* sWo  = smem + 19328;
    float* sWp  = smem + 19392;
    float* sbp  = smem + 19536;
    float* sSeq = smem + 19552;

    const int tid = threadIdx.x;
    const int bn0 = blockIdx.x * 256;

    if (tid < 64) sWo[tid] = Wo[tid];
    if (tid < P_) sbp[tid] = bp[tid];
    for (int k = tid; k < P_ * T_; k += 128) sWp[k] = Wp[k];

    // stage x for both sequences (padded rows of 25 floats)
#pragma unroll
    for (int s = 0; s < 2; s++) {
        int row = tid + s * 128;
        const float4* gx = reinterpret_cast<const float4*>(x) + (size_t)(bn0 + row) * 6;
#pragma unroll
        for (int u = 0; u < 6; u++) {
            float4 v = gx[u];
            sx[row * 25 + 4 * u + 0] = v.x;
            sx[row * 25 + 4 * u + 1] = v.y;
            sx[row * 25 + 4 * u + 2] = v.z;
            sx[row * 25 + 4 * u + 3] = v.w;
        }
    }

    u64 hA2[32], hB2[32];
    float hA[64], hB[64];   // local memory (dynamic index), lane-interleaved
#pragma unroll
    for (int k = 0; k < 32; k++) { hA2[k] = 0ull; hB2[k] = 0ull; }
    for (int j = 0; j < 64; j++) { hA[j] = 0.0f; hB[j] = 0.0f; }

    const float bo0 = __ldg(bo);

    for (int t = 0; t < T_; t++) {
        __syncthreads();
        {
            const float4* wr4 = reinterpret_cast<const float4*>(g_Wrh + t * 4096);
            const float4* wz4 = reinterpret_cast<const float4*>(g_Wzh + t * 4096);
            const float4* wc4 = reinterpret_cast<const float4*>(g_Wch + t * 4096);
            float4* dW = reinterpret_cast<float4*>(sW);
#pragma unroll
            for (int k = 0; k < 8; k++) {
                dW[k * 128 + tid]        = wr4[k * 128 + tid];
                dW[1024 + k * 128 + tid] = wz4[k * 128 + tid];
                dW[2048 + k * 128 + tid] = wc4[k * 128 + tid];
            }
            sWx[tid]       = g_Wrx[t * 128 + tid];
            sWx[128 + tid] = g_Wzx[t * 128 + tid];
            sWx[256 + tid] = g_Wcx[t * 128 + tid];
            if (tid < 64) {
                sb[tid]       = g_brx[t * 64 + tid] + g_brh[t * 64 + tid];
                sb[64 + tid]  = g_bzx[t * 64 + tid] + g_bzh[t * 64 + tid];
                sb[128 + tid] = g_bcx[t * 64 + tid];
                sb[192 + tid] = g_bch[t * 64 + tid];
            }
        }
        __syncthreads();

        const float xA0 = sx[tid * 25 + 2 * t];
        const float xA1 = sx[tid * 25 + 2 * t + 1];
        const float xB0 = sx[(tid + 128) * 25 + 2 * t];
        const float xB1 = sx[(tid + 128) * 25 + 2 * t + 1];
        float oA = bo0, oB = bo0;

#pragma unroll 2
        for (int i = 0; i < 64; i++) {
            u64 arA = 0ull, azA = 0ull, acA = 0ull;
            u64 arB = 0ull, azB = 0ull, acB = 0ull;
            const ulonglong2* wr = reinterpret_cast<const ulonglong2*>(sW + i * 64);
            const ulonglong2* wq = reinterpret_cast<const ulonglong2*>(sW + 4096 + i * 64);
            const ulonglong2* wc = reinterpret_cast<const ulonglong2*>(sW + 8192 + i * 64);
#pragma unroll
            for (int q = 0; q < 16; q++) {
                ulonglong2 a = wr[q];
                ulonglong2 b = wq[q];
                ulonglong2 c = wc[q];
                arA = fma2(hA2[2 * q], a.x, arA);
                arA = fma2(hA2[2 * q + 1], a.y, arA);
                arB = fma2(hB2[2 * q], a.x, arB);
                arB = fma2(hB2[2 * q + 1], a.y, arB);
                azA = fma2(hA2[2 * q], b.x, azA);
                azA = fma2(hA2[2 * q + 1], b.y, azA);
                azB = fma2(hB2[2 * q], b.x, azB);
                azB = fma2(hB2[2 * q + 1], b.y, azB);
                acA = fma2(hA2[2 * q], c.x, acA);
                acA = fma2(hA2[2 * q + 1], c.y, acA);
                acB = fma2(hB2[2 * q], c.x, acB);
                acB = fma2(hB2[2 * q + 1], c.y, acB);
            }
            float wxr0 = sWx[2 * i], wxr1 = sWx[2 * i + 1];
            float wxz0 = sWx[128 + 2 * i], wxz1 = sWx[128 + 2 * i + 1];
            float wxc0 = sWx[256 + 2 * i], wxc1 = sWx[256 + 2 * i + 1];
            float br = sb[i], bz2 = sb[64 + i], bcx = sb[128 + i], bch = sb[192 + i];

            float2 v;
            v = unpack2(arA); float drA = v.x + v.y;
            v = unpack2(azA); float dzA = v.x + v.y;
            v = unpack2(acA); float dcA = v.x + v.y;
            v = unpack2(arB); float drB = v.x + v.y;
            v = unpack2(azB); float dzB = v.x + v.y;
            v = unpack2(acB); float dcB = v.x + v.y;

            float rA = sigf(drA + xA0 * wxr0 + xA1 * wxr1 + br);
            float zA = sigf(dzA + xA0 * wxz0 + xA1 * wxz1 + bz2);
            float cA = tanhf_fast(xA0 * wxc0 + xA1 * wxc1 + bcx + rA * (dcA + bch));
            float hnA = (1.0f - zA) * cA + zA * hA[i];
            hA[i] = hnA;
            oA = fmaf(hnA, sWo[i], oA);

            float rB = sigf(drB + xB0 * wxr0 + xB1 * wxr1 + br);
            float zB = sigf(dzB + xB0 * wxz0 + xB1 * wxz1 + bz2);
            float cB = tanhf_fast(xB0 * wxc0 + xB1 * wxc1 + bcx + rB * (dcB + bch));
            float hnB = (1.0f - zB) * cB + zB * hB[i];
            hB[i] = hnB;
            oB = fmaf(hnB, sWo[i], oB);
        }
        sSeq[t * 256 + tid]       = fmaxf(oA, 0.0f);
        sSeq[t * 256 + 128 + tid] = fmaxf(oB, 0.0f);

#pragma unroll
        for (int k = 0; k < 32; k++) {
            hA2[k] = pack2(hA[2 * k], hA[2 * k + 1]);
            hB2[k] = pack2(hB[2 * k], hB[2 * k + 1]);
        }
    }

    // predictor for both sequences
#pragma unroll
    for (int s = 0; s < 2; s++) {
        int col = tid + s * 128;
        const size_t base = (size_t)(bn0 + col) * P_;
#pragma unroll
        for (int p = 0; p < P_; p++) {
            float acc = sbp[p];
#pragma unroll
            for (int t = 0; t < T_; t++)
                acc = fmaf(sSeq[t * 256 + col], sWp[p * T_ + t], acc);
            out[base + p] = acc;
            if (dup) out[NPRED + base + p] = acc;
        }
    }
}

extern "C" void kernel_launch(void* const* d_in, const int* in_sizes, int n_in,
                              void* d_out, int out_size) {
    const float* x  = (const float*)d_in[0];
    const float* wz = (const float*)d_in[2];
    const float* bz = (const float*)d_in[3];
    const float* Wl_rx = (const float*)d_in[4];
    const float* bl_rx = (const float*)d_in[5];
    const float* Wb_rx = (const float*)d_in[6];
    const float* bb_rx = (const float*)d_in[7];
    const float* Wl_rh = (const float*)d_in[8];
    const float* bl_rh = (const float*)d_in[9];
    const float* Wb_rh = (const float*)d_in[10];
    const float* bb_rh = (const float*)d_in[11];
    const float* Wl_zx = (const float*)d_in[12];
    const float* bl_zx = (const float*)d_in[13];
    const float* Wb_zx = (const float*)d_in[14];
    const float* bb_zx = (const float*)d_in[15];
    const float* Wl_zh = (const float*)d_in[16];
    const float* bl_zh = (const float*)d_in[17];
    const float* Wb_zh = (const float*)d_in[18];
    const float* bb_zh = (const float*)d_in[19];
    const float* Wl_cx = (const float*)d_in[20];
    const float* bl_cx = (const float*)d_in[21];
    const float* Wb_cx = (const float*)d_in[22];
    const float* bb_cx = (const float*)d_in[23];
    const float* Wl_ch = (const float*)d_in[24];
    const float* bl_ch = (const float*)d_in[25];
    const float* Wb_ch = (const float*)d_in[26];
    const float* bb_ch = (const float*)d_in[27];
    const float* Wo = (const float*)d_in[28];
    const float* bo = (const float*)d_in[29];
    const float* Wp = (const float*)d_in[30];
    const float* bp = (const float*)d_in[31];
    float* out = (float*)d_out;

    precompute_kernel<<<612, 256>>>(
        wz, bz,
        Wl_rx, bl_rx, Wb_rx, bb_rx,
        Wl_rh, bl_rh, Wb_rh, bb_rh,
        Wl_zx, bl_zx, Wb_zx, bb_zx,
        Wl_zh, bl_zh, Wb_zh, bb_zh,
        Wl_cx, bl_cx, Wb_cx, bb_cx,
        Wl_ch, bl_ch, Wb_ch, bb_ch);

    int dup = (out_size >= 2 * NPRED) ? 1 : 0;
    cudaFuncSetAttribute(gru_kernel,
                         cudaFuncAttributeMaxDynamicSharedMemorySize, SMEM_BYTES);
    gru_kernel<<<512, 128, SMEM_BYTES>>>(x, Wo, bo, Wp, bp, out, dup);
}

// round 7
// speedup vs baseline: 2.4955x; 1.9917x over previous
#include <cuda_runtime.h>
#include <cuda_bf16.h>
#include <stdint.h>

#define T_ 12
#define BN_TOT 131072
#define NPRED (BN_TOT * 12)

__device__ __align__(16) uint32_t g_Bh[T_ * 6144];
__device__ __align__(16) uint32_t g_Bl[T_ * 6144];
__device__ __align__(16) float g_epi[T_ * 64 * 12];

struct Meta { const float *wz, *bz, *Wl[6], *bl[6], *Wb[6], *bb[6], *Wo; };

__device__ __forceinline__ float dot32(const float* a, const float* b) {
    float s = 0.f;
#pragma unroll
    for (int m = 0; m < 32; m++) s = fmaf(a[m], b[m], s);
    return s;
}
__device__ __forceinline__ uint32_t pkbf(float a, float b) {
    return ((uint32_t)__bfloat16_as_ushort(__float2bfloat16(b)) << 16) |
           __bfloat16_as_ushort(__float2bfloat16(a));
}
__device__ __forceinline__ float bflo(uint32_t w) {
    return __bfloat162float(__ushort_as_bfloat16((unsigned short)(w & 0xFFFF)));
}
__device__ __forceinline__ float bfhi(uint32_t w) {
    return __bfloat162float(__ushort_as_bfloat16((unsigned short)(w >> 16)));
}
__device__ __forceinline__ float sigf(float x) { return __fdividef(1.0f, 1.0f + __expf(-x)); }
__device__ __forceinline__ float tanhf_fast(float x) {
    float e = __expf(2.0f * x);
    return 1.0f - __fdividef(2.0f, e + 1.0f);
}

// B fragment-ready: word idx = t*6144 + (g*8+j)*256 + ks*64 + lane*2 + half
// word = {B[n,k0], B[n,k0+1]} bf16x2, n = nt*8 + lane/4, k0 = ks*16 + (lane%4)*2 + half*8
__global__ void pre_kernel(Meta p) {
    int idx = blockIdx.x * 256 + threadIdx.x;
    if (idx < 73728) {
        int t = idx / 6144, r = idx % 6144;
        int nt = r / 256, r2 = r % 256;
        int ks = r2 / 64, r3 = r2 % 64;
        int ln = r3 >> 1, half = r3 & 1;
        int n = nt * 8 + (ln >> 2);
        int k0 = ks * 16 + (ln & 3) * 2 + half * 8;
        int g = n >> 6, i = n & 63;
        const float* wzt = p.wz + t * 32;
        float s0 = dot32(wzt, p.Wl[2 * g + 1] + (i * 64 + k0) * 32) + p.bl[2 * g + 1][i * 64 + k0];
        float s1 = dot32(wzt, p.Wl[2 * g + 1] + (i * 64 + k0 + 1) * 32) + p.bl[2 * g + 1][i * 64 + k0 + 1];
        uint32_t wh = pkbf(s0, s1);
        g_Bh[idx] = wh;
        g_Bl[idx] = pkbf(s0 - bflo(wh), s1 - bfhi(wh));
    } else if (idx < 73728 + 8448) {
        int e = idx - 73728;
        int t = e / 704, r = e % 704;
        int i = r / 11, s2 = r % 11;
        float v;
        if (s2 < 6) {
            int g = s2 >> 1, d = s2 & 1;
            v = dot32(p.wz + t * 32, p.Wl[2 * g] + (i * 2 + d) * 32) + p.bl[2 * g][i * 2 + d];
        } else if (s2 == 6)
            v = dot32(p.bz + t * 32, p.Wb[0] + i * 32) + p.bb[0][i]
              + dot32(p.bz + t * 32, p.Wb[1] + i * 32) + p.bb[1][i];
        else if (s2 == 7)
            v = dot32(p.bz + t * 32, p.Wb[2] + i * 32) + p.bb[2][i]
              + dot32(p.bz + t * 32, p.Wb[3] + i * 32) + p.bb[3][i];
        else if (s2 == 8)
            v = dot32(p.bz + t * 32, p.Wb[4] + i * 32) + p.bb[4][i];
        else if (s2 == 9)
            v = dot32(p.bz + t * 32, p.Wb[5] + i * 32) + p.bb[5][i];
        else
            v = p.Wo[i];
        g_epi[(t * 64 + i) * 12 + s2] = v;
    }
}

#define MMA(d, a, b0_, b1_) \
    asm volatile("mma.sync.aligned.m16n8k16.row.col.f32.bf16.bf16.f32 " \
        "{%0,%1,%2,%3}, {%4,%5,%6,%7}, {%8,%9}, {%0,%1,%2,%3};" \
        : "+f"((d)[0]), "+f"((d)[1]), "+f"((d)[2]), "+f"((d)[3]) \
        : "r"((a)[0]), "r"((a)[1]), "r"((a)[2]), "r"((a)[3]), "r"(b0_), "r"(b1_))

#define SM_BH  0
#define SM_BL  24576
#define SM_X   49152
#define SM_SEQ 61952
#define SM_EPI 68096
#define SM_WP  71168
#define SM_BP  71744
#define SM_HN  71808
#define SMEM_BYTES (71808 + 32768)

__global__ void __launch_bounds__(128, 2)
gru_mma(const float* __restrict__ x, const float* __restrict__ bo,
        const float* __restrict__ Wp, const float* __restrict__ bp,
        float* __restrict__ out, int dup)
{
    extern __shared__ char smem[];
    const int tid = threadIdx.x, lane = tid & 31, wid = tid >> 5;
    const int bn0 = blockIdx.x * 128;
    const int g4 = lane >> 2, q2 = (lane & 3) * 2;

    float* sx = (float*)(smem + SM_X);
    float* sSeq = (float*)(smem + SM_SEQ);
    uint32_t* sHn = (uint32_t*)(smem + SM_HN);   // [64 words][128 tid] hi(0..31) lo(32..63)
    if (tid < 12) ((float*)(smem + SM_BP))[tid] = bp[tid];
    for (int k = tid; k < 144; k += 128) ((float*)(smem + SM_WP))[k] = Wp[k];
    {
        const float4* gx = (const float4*)x + (size_t)(bn0 + tid) * 6;
#pragma unroll
        for (int u = 0; u < 6; u++) {
            float4 v = gx[u];
            sx[tid * 25 + 4 * u] = v.x; sx[tid * 25 + 4 * u + 1] = v.y;
            sx[tid * 25 + 4 * u + 2] = v.z; sx[tid * 25 + 4 * u + 3] = v.w;
        }
    }

    uint32_t Ah[2][4][4], Al[2][4][4];
#pragma unroll
    for (int a = 0; a < 2; a++)
#pragma unroll
        for (int b = 0; b < 4; b++)
#pragma unroll
            for (int c = 0; c < 4; c++) { Ah[a][b][c] = 0u; Al[a][b][c] = 0u; }
    const float bo0 = __ldg(bo);

    for (int t = 0; t < T_; t++) {
        __syncthreads();
        {
            const uint4* gb = (const uint4*)(g_Bh + t * 6144);
            const uint4* gl = (const uint4*)(g_Bl + t * 6144);
            uint4* db = (uint4*)(smem + SM_BH);
            uint4* dl = (uint4*)(smem + SM_BL);
#pragma unroll
            for (int k = 0; k < 12; k++) {
                db[k * 128 + tid] = gb[k * 128 + tid];
                dl[k * 128 + tid] = gl[k * 128 + tid];
            }
            const uint4* ge = (const uint4*)(g_epi + t * 768);
            uint4* de = (uint4*)(smem + SM_EPI);
            de[tid] = ge[tid];
            if (tid < 64) de[128 + tid] = ge[128 + tid];
        }
        __syncthreads();

        float x0[4], x1[4], oacc[4];
#pragma unroll
        for (int rr = 0; rr < 4; rr++) {
            int row = wid * 32 + g4 + rr * 8;
            x0[rr] = sx[row * 25 + 2 * t];
            x1[rr] = sx[row * 25 + 2 * t + 1];
            oacc[rr] = 0.f;
        }
        const uint32_t* sBh = (const uint32_t*)(smem + SM_BH);
        const uint32_t* sBl = (const uint32_t*)(smem + SM_BL);
        const float4* sE = (const float4*)(smem + SM_EPI);

#pragma unroll
        for (int j = 0; j < 8; j++) {
            float d[3][2][4];
#pragma unroll
            for (int a = 0; a < 3; a++)
#pragma unroll
                for (int b = 0; b < 2; b++)
#pragma unroll
                    for (int c = 0; c < 4; c++) d[a][b][c] = 0.f;
#pragma unroll
            for (int ks = 0; ks < 4; ks++) {
#pragma unroll
                for (int g3 = 0; g3 < 3; g3++) {
                    int bi = ((g3 * 8 + j) * 4 + ks) * 64 + lane * 2;
                    uint32_t bh0 = sBh[bi], bh1 = sBh[bi + 1];
                    uint32_t bl0 = sBl[bi], bl1 = sBl[bi + 1];
#pragma unroll
                    for (int mt = 0; mt < 2; mt++) {
                        MMA(d[g3][mt], Ah[mt][ks], bh0, bh1);
                        MMA(d[g3][mt], Al[mt][ks], bh0, bh1);
                        MMA(d[g3][mt], Ah[mt][ks], bl0, bl1);
                    }
                }
            }
            int i0 = j * 8 + q2;
            float4 e0a = sE[i0 * 3], e1a = sE[i0 * 3 + 1], e2a = sE[i0 * 3 + 2];
            float4 e0b = sE[i0 * 3 + 3], e1b = sE[i0 * 3 + 4], e2b = sE[i0 * 3 + 5];
            int ks = j >> 1, rb = (j & 1) * 2;
#pragma unroll
            for (int mt = 0; mt < 2; mt++) {
#pragma unroll
                for (int pp = 0; pp < 2; pp++) {
                    int rr = mt * 2 + pp;
                    uint32_t oh = Ah[mt][ks][rb + pp], ol = Al[mt][ks][rb + pp];
                    float hold0 = bflo(oh) + bflo(ol);
                    float hold1 = bfhi(oh) + bfhi(ol);
                    float dr0 = d[0][mt][pp * 2], dr1 = d[0][mt][pp * 2 + 1];
                    float dz0 = d[1][mt][pp * 2], dz1 = d[1][mt][pp * 2 + 1];
                    float dc0 = d[2][mt][pp * 2], dc1 = d[2][mt][pp * 2 + 1];
                    float r0 = sigf(dr0 + x0[rr] * e0a.x + x1[rr] * e0a.y + e1a.z);
                    float z0 = sigf(dz0 + x0[rr] * e0a.z + x1[rr] * e0a.w + e1a.w);
                    float c0 = tanhf_fast(x0[rr] * e1a.x + x1[rr] * e1a.y + e2a.x + r0 * (dc0 + e2a.y));
                    float hn0 = (1.f - z0) * c0 + z0 * hold0;
                    float r1 = sigf(dr1 + x0[rr] * e0b.x + x1[rr] * e0b.y + e1b.z);
                    float z1 = sigf(dz1 + x0[rr] * e0b.z + x1[rr] * e0b.w + e1b.w);
                    float c1 = tanhf_fast(x0[rr] * e1b.x + x1[rr] * e1b.y + e2b.x + r1 * (dc1 + e2b.y));
                    float hn1 = (1.f - z1) * c1 + z1 * hold1;
                    oacc[rr] = fmaf(hn0, e2a.z, oacc[rr]);
                    oacc[rr] = fmaf(hn1, e2b.z, oacc[rr]);
                    // Stage new h to private smem; A fragments stay = h(t-1)
                    // until ALL n-tiles' MMAs for this step are complete.
                    uint32_t nh = pkbf(hn0, hn1);
                    uint32_t nl = pkbf(hn0 - bflo(nh), hn1 - bfhi(nh));
                    int w = ((mt * 4 + ks) * 4 + rb + pp);
                    sHn[w * 128 + tid] = nh;
                    sHn[(32 + w) * 128 + tid] = nl;
                }
            }
        }
        // all MMAs of step t done -> safe to load h(t) into A fragments
#pragma unroll
        for (int mt = 0; mt < 2; mt++)
#pragma unroll
            for (int ks = 0; ks < 4; ks++)
#pragma unroll
                for (int c = 0; c < 4; c++) {
                    int w = (mt * 4 + ks) * 4 + c;
                    Ah[mt][ks][c] = sHn[w * 128 + tid];
                    Al[mt][ks][c] = sHn[(32 + w) * 128 + tid];
                }
#pragma unroll
        for (int rr = 0; rr < 4; rr++) {
            float v = oacc[rr];
            v += __shfl_xor_sync(0xffffffffu, v, 1);
            v += __shfl_xor_sync(0xffffffffu, v, 2);
            v = fmaxf(v + bo0, 0.f);
            sSeq[t * 128 + wid * 32 + g4 + rr * 8] = v;  // quad lanes write same value
        }
    }
    __syncthreads();

    const float* sWp = (const float*)(smem + SM_WP);
    const float* sbp = (const float*)(smem + SM_BP);
    float sq[12];
#pragma unroll
    for (int tt = 0; tt < 12; tt++) sq[tt] = sSeq[tt * 128 + tid];
    float pr[12];
#pragma unroll
    for (int p = 0; p < 12; p++) {
        float a = sbp[p];
#pragma unroll
        for (int tt = 0; tt < 12; tt++) a = fmaf(sq[tt], sWp[p * 12 + tt], a);
        pr[p] = a;
    }
    size_t base = (size_t)(bn0 + tid) * 12;
    float4* o4 = (float4*)(out + base);
    o4[0] = make_float4(pr[0], pr[1], pr[2], pr[3]);
    o4[1] = make_float4(pr[4], pr[5], pr[6], pr[7]);
    o4[2] = make_float4(pr[8], pr[9], pr[10], pr[11]);
    if (dup) {
        float4* d4 = (float4*)(out + NPRED + base);
        d4[0] = make_float4(pr[0], pr[1], pr[2], pr[3]);
        d4[1] = make_float4(pr[4], pr[5], pr[6], pr[7]);
        d4[2] = make_float4(pr[8], pr[9], pr[10], pr[11]);
    }
}

extern "C" void kernel_launch(void* const* d_in, const int* in_sizes, int n_in,
                              void* d_out, int out_size) {
    Meta m;
    m.wz = (const float*)d_in[2];
    m.bz = (const float*)d_in[3];
    for (int g = 0; g < 6; g++) {   // rx, rh, zx, zh, cx, ch
        m.Wl[g] = (const float*)d_in[4 + g * 4];
        m.bl[g] = (const float*)d_in[5 + g * 4];
        m.Wb[g] = (const float*)d_in[6 + g * 4];
        m.bb[g] = (const float*)d_in[7 + g * 4];
    }
    m.Wo = (const float*)d_in[28];
    const float* x  = (const float*)d_in[0];
    const float* bo = (const float*)d_in[29];
    const float* Wp = (const float*)d_in[30];
    const float* bp = (const float*)d_in[31];
    float* out = (float*)d_out;

    pre_kernel<<<321, 256>>>(m);

    int dup = (out_size >= 2 * NPRED) ? 1 : 0;
    cudaFuncSetAttribute(gru_mma, cudaFuncAttributeMaxDynamicSharedMemorySize, SMEM_BYTES);
    gru_mma<<<1024, 128, SMEM_BYTES>>>(x, bo, Wp, bp, out, dup);
}

// round 8
// speedup vs baseline: 2.8811x; 1.1545x over previous
#include <cuda_runtime.h>
#include <cuda_bf16.h>
#include <stdint.h>

#define T_ 12
#define BN_TOT 131072
#define NPRED (BN_TOT * 12)

__device__ __align__(16) uint32_t g_Bh[T_ * 6144];
__device__ __align__(16) uint32_t g_Bl[T_ * 6144];
__device__ __align__(16) float g_epi[T_ * 64 * 12];

struct Meta { const float *wz, *bz, *Wl[6], *bl[6], *Wb[6], *bb[6], *Wo; };

__device__ __forceinline__ float dot32(const float* a, const float* b) {
    float s = 0.f;
#pragma unroll
    for (int m = 0; m < 32; m++) s = fmaf(a[m], b[m], s);
    return s;
}
__device__ __forceinline__ uint32_t pkbf(float a, float b) {
    return ((uint32_t)__bfloat16_as_ushort(__float2bfloat16(b)) << 16) |
           __bfloat16_as_ushort(__float2bfloat16(a));
}
__device__ __forceinline__ float bflo(uint32_t w) {
    return __bfloat162float(__ushort_as_bfloat16((unsigned short)(w & 0xFFFF)));
}
__device__ __forceinline__ float bfhi(uint32_t w) {
    return __bfloat162float(__ushort_as_bfloat16((unsigned short)(w >> 16)));
}
__device__ __forceinline__ float tanh_ap(float x) {
    float y;
    asm("tanh.approx.f32 %0, %1;" : "=f"(y) : "f"(x));
    return y;
}
__device__ __forceinline__ float tanhf_exact(float x) {
    float e = __expf(2.0f * x);
    return 1.0f - __fdividef(2.0f, e + 1.0f);
}

// B fragment-ready: word idx = t*6144 + (g*8+j)*256 + ks*64 + lane*2 + half
// word = {B[n,k0], B[n,k0+1]} bf16x2, n = nt*8 + lane/4, k0 = ks*16 + (lane%4)*2 + half*8
// r/z gate rows (g<2) are PRE-SCALED by 0.5 (sigmoid-via-tanh folding).
__global__ void pre_kernel(Meta p) {
    int idx = blockIdx.x * 256 + threadIdx.x;
    if (idx < 73728) {
        int t = idx / 6144, r = idx % 6144;
        int nt = r / 256, r2 = r % 256;
        int ks = r2 / 64, r3 = r2 % 64;
        int ln = r3 >> 1, half = r3 & 1;
        int n = nt * 8 + (ln >> 2);
        int k0 = ks * 16 + (ln & 3) * 2 + half * 8;
        int g = n >> 6, i = n & 63;
        float gs = (g < 2) ? 0.5f : 1.0f;
        const float* wzt = p.wz + t * 32;
        float s0 = gs * (dot32(wzt, p.Wl[2 * g + 1] + (i * 64 + k0) * 32) + p.bl[2 * g + 1][i * 64 + k0]);
        float s1 = gs * (dot32(wzt, p.Wl[2 * g + 1] + (i * 64 + k0 + 1) * 32) + p.bl[2 * g + 1][i * 64 + k0 + 1]);
        uint32_t wh = pkbf(s0, s1);
        g_Bh[idx] = wh;
        g_Bl[idx] = pkbf(s0 - bflo(wh), s1 - bfhi(wh));
    } else if (idx < 73728 + 8448) {
        int e = idx - 73728;
        int t = e / 704, r = e % 704;
        int i = r / 11, s2 = r % 11;
        float v;
        if (s2 < 6) {
            int g = s2 >> 1, d = s2 & 1;
            v = dot32(p.wz + t * 32, p.Wl[2 * g] + (i * 2 + d) * 32) + p.bl[2 * g][i * 2 + d];
            if (g < 2) v *= 0.5f;     // fold sigmoid /2 into r/z x-coeffs
        } else if (s2 == 6)
            v = 0.5f * (dot32(p.bz + t * 32, p.Wb[0] + i * 32) + p.bb[0][i]
                      + dot32(p.bz + t * 32, p.Wb[1] + i * 32) + p.bb[1][i]);
        else if (s2 == 7)
            v = 0.5f * (dot32(p.bz + t * 32, p.Wb[2] + i * 32) + p.bb[2][i]
                      + dot32(p.bz + t * 32, p.Wb[3] + i * 32) + p.bb[3][i]);
        else if (s2 == 8)
            v = dot32(p.bz + t * 32, p.Wb[4] + i * 32) + p.bb[4][i];
        else if (s2 == 9)
            v = dot32(p.bz + t * 32, p.Wb[5] + i * 32) + p.bb[5][i];
        else
            v = p.Wo[i];
        g_epi[(t * 64 + i) * 12 + s2] = v;
    }
}

#define MMA(d, a, b0_, b1_) \
    asm volatile("mma.sync.aligned.m16n8k16.row.col.f32.bf16.bf16.f32 " \
        "{%0,%1,%2,%3}, {%4,%5,%6,%7}, {%8,%9}, {%0,%1,%2,%3};" \
        : "+f"((d)[0]), "+f"((d)[1]), "+f"((d)[2]), "+f"((d)[3]) \
        : "r"((a)[0]), "r"((a)[1]), "r"((a)[2]), "r"((a)[3]), "r"(b0_), "r"(b1_))

#define SM_BH  0
#define SM_BL  24576
#define SM_X   49152
#define SM_SEQ 61952
#define SM_EPI 68096
#define SM_WP  71168
#define SM_BP  71744
#define SM_HN  71808
#define SMEM_BYTES (71808 + 32768)

// Epilogue per element (r/z via tanh.approx with pre-folded /2; c via exact exp):
//   tr = tanh(argr'); tz = tanh(argz');  r = 0.5+0.5tr; z = 0.5+0.5tz
//   argc = xcb + 0.5*(1+tr)*(dc+bch);  c = tanh_exact(argc)
//   hn = (1-z)c + z*hold = 0.5*((hold+c) + tz*(hold-c))
__global__ void __launch_bounds__(128, 2)
gru_mma(const float* __restrict__ x, const float* __restrict__ bo,
        const float* __restrict__ Wp, const float* __restrict__ bp,
        float* __restrict__ out, int dup)
{
    extern __shared__ char smem[];
    const int tid = threadIdx.x, lane = tid & 31, wid = tid >> 5;
    const int bn0 = blockIdx.x * 128;
    const int g4 = lane >> 2, q2 = (lane & 3) * 2;

    float* sx = (float*)(smem + SM_X);
    float* sSeq = (float*)(smem + SM_SEQ);
    uint32_t* sHn = (uint32_t*)(smem + SM_HN);   // [64 words][128 tid] hi(0..31) lo(32..63)
    if (tid < 12) ((float*)(smem + SM_BP))[tid] = bp[tid];
    for (int k = tid; k < 144; k += 128) ((float*)(smem + SM_WP))[k] = Wp[k];
    {
        const float4* gx = (const float4*)x + (size_t)(bn0 + tid) * 6;
#pragma unroll
        for (int u = 0; u < 6; u++) {
            float4 v = gx[u];
            sx[tid * 25 + 4 * u] = v.x; sx[tid * 25 + 4 * u + 1] = v.y;
            sx[tid * 25 + 4 * u + 2] = v.z; sx[tid * 25 + 4 * u + 3] = v.w;
        }
    }

    uint32_t Ah[2][4][4], Al[2][4][4];
#pragma unroll
    for (int a = 0; a < 2; a++)
#pragma unroll
        for (int b = 0; b < 4; b++)
#pragma unroll
            for (int c = 0; c < 4; c++) { Ah[a][b][c] = 0u; Al[a][b][c] = 0u; }
    const float bo0 = __ldg(bo);

    for (int t = 0; t < T_; t++) {
        __syncthreads();
        {
            const uint4* gb = (const uint4*)(g_Bh + t * 6144);
            const uint4* gl = (const uint4*)(g_Bl + t * 6144);
            uint4* db = (uint4*)(smem + SM_BH);
            uint4* dl = (uint4*)(smem + SM_BL);
#pragma unroll
            for (int k = 0; k < 12; k++) {
                db[k * 128 + tid] = gb[k * 128 + tid];
                dl[k * 128 + tid] = gl[k * 128 + tid];
            }
            const uint4* ge = (const uint4*)(g_epi + t * 768);
            uint4* de = (uint4*)(smem + SM_EPI);
            de[tid] = ge[tid];
            if (tid < 64) de[128 + tid] = ge[128 + tid];
        }
        __syncthreads();

        float x0[4], x1[4], oacc[4];
#pragma unroll
        for (int rr = 0; rr < 4; rr++) {
            int row = wid * 32 + g4 + rr * 8;
            x0[rr] = sx[row * 25 + 2 * t];
            x1[rr] = sx[row * 25 + 2 * t + 1];
            oacc[rr] = 0.f;
        }
        const uint32_t* sBh = (const uint32_t*)(smem + SM_BH);
        const uint32_t* sBl = (const uint32_t*)(smem + SM_BL);
        const float4* sE = (const float4*)(smem + SM_EPI);

#pragma unroll
        for (int j = 0; j < 8; j++) {
            float d[3][2][4];
#pragma unroll
            for (int a = 0; a < 3; a++)
#pragma unroll
                for (int b = 0; b < 2; b++)
#pragma unroll
                    for (int c = 0; c < 4; c++) d[a][b][c] = 0.f;
#pragma unroll
            for (int ks = 0; ks < 4; ks++) {
#pragma unroll
                for (int g3 = 0; g3 < 3; g3++) {
                    int bi = ((g3 * 8 + j) * 4 + ks) * 64 + lane * 2;
                    uint32_t bh0 = sBh[bi], bh1 = sBh[bi + 1];
                    uint32_t bl0 = sBl[bi], bl1 = sBl[bi + 1];
#pragma unroll
                    for (int mt = 0; mt < 2; mt++) {
                        MMA(d[g3][mt], Ah[mt][ks], bh0, bh1);
                        MMA(d[g3][mt], Al[mt][ks], bh0, bh1);
                        MMA(d[g3][mt], Ah[mt][ks], bl0, bl1);
                    }
                }
            }
            int i0 = j * 8 + q2;
            float4 e0a = sE[i0 * 3], e1a = sE[i0 * 3 + 1], e2a = sE[i0 * 3 + 2];
            float4 e0b = sE[i0 * 3 + 3], e1b = sE[i0 * 3 + 4], e2b = sE[i0 * 3 + 5];
            int ks = j >> 1, rb = (j & 1) * 2;
#pragma unroll
            for (int mt = 0; mt < 2; mt++) {
#pragma unroll
                for (int pp = 0; pp < 2; pp++) {
                    int rr = mt * 2 + pp;
                    uint32_t oh = Ah[mt][ks][rb + pp], ol = Al[mt][ks][rb + pp];
                    float hold0 = bflo(oh) + bflo(ol);
                    float hold1 = bfhi(oh) + bfhi(ol);
                    float dr0 = d[0][mt][pp * 2], dr1 = d[0][mt][pp * 2 + 1];
                    float dz0 = d[1][mt][pp * 2], dz1 = d[1][mt][pp * 2 + 1];
                    float dc0 = d[2][mt][pp * 2], dc1 = d[2][mt][pp * 2 + 1];

                    float tr0 = tanh_ap(dr0 + x0[rr] * e0a.x + x1[rr] * e0a.y + e1a.z);
                    float tz0 = tanh_ap(dz0 + x0[rr] * e0a.z + x1[rr] * e0a.w + e1a.w);
                    float u0 = dc0 + e2a.y;
                    float xcb0 = x0[rr] * e1a.x + x1[rr] * e1a.y + e2a.x;
                    float c0 = tanhf_exact(fmaf(0.5f, fmaf(tr0, u0, u0), xcb0));
                    float hn0 = 0.5f * fmaf(tz0, hold0 - c0, hold0 + c0);

                    float tr1 = tanh_ap(dr1 + x0[rr] * e0b.x + x1[rr] * e0b.y + e1b.z);
                    float tz1 = tanh_ap(dz1 + x0[rr] * e0b.z + x1[rr] * e0b.w + e1b.w);
                    float u1 = dc1 + e2b.y;
                    float xcb1 = x0[rr] * e1b.x + x1[rr] * e1b.y + e2b.x;
                    float c1 = tanhf_exact(fmaf(0.5f, fmaf(tr1, u1, u1), xcb1));
                    float hn1 = 0.5f * fmaf(tz1, hold1 - c1, hold1 + c1);

                    oacc[rr] = fmaf(hn0, e2a.z, oacc[rr]);
                    oacc[rr] = fmaf(hn1, e2b.z, oacc[rr]);
                    uint32_t nh = pkbf(hn0, hn1);
                    uint32_t nl = pkbf(hn0 - bflo(nh), hn1 - bfhi(nh));
                    int w = ((mt * 4 + ks) * 4 + rb + pp);
                    sHn[w * 128 + tid] = nh;
                    sHn[(32 + w) * 128 + tid] = nl;
                }
            }
        }
        // all MMAs of step t done -> safe to load h(t) into A fragments
#pragma unroll
        for (int mt = 0; mt < 2; mt++)
#pragma unroll
            for (int ks = 0; ks < 4; ks++)
#pragma unroll
                for (int c = 0; c < 4; c++) {
                    int w = (mt * 4 + ks) * 4 + c;
                    Ah[mt][ks][c] = sHn[w * 128 + tid];
                    Al[mt][ks][c] = sHn[(32 + w) * 128 + tid];
                }
#pragma unroll
        for (int rr = 0; rr < 4; rr++) {
            float v = oacc[rr];
            v += __shfl_xor_sync(0xffffffffu, v, 1);
            v += __shfl_xor_sync(0xffffffffu, v, 2);
            v = fmaxf(v + bo0, 0.f);
            sSeq[t * 128 + wid * 32 + g4 + rr * 8] = v;  // quad lanes write same value
        }
    }
    __syncthreads();

    const float* sWp = (const float*)(smem + SM_WP);
    const float* sbp = (const float*)(smem + SM_BP);
    float sq[12];
#pragma unroll
    for (int tt = 0; tt < 12; tt++) sq[tt] = sSeq[tt * 128 + tid];
    float pr[12];
#pragma unroll
    for (int p = 0; p < 12; p++) {
        float a = sbp[p];
#pragma unroll
        for (int tt = 0; tt < 12; tt++) a = fmaf(sq[tt], sWp[p * 12 + tt], a);
        pr[p] = a;
    }
    size_t base = (size_t)(bn0 + tid) * 12;
    float4* o4 = (float4*)(out + base);
    o4[0] = make_float4(pr[0], pr[1], pr[2], pr[3]);
    o4[1] = make_float4(pr[4], pr[5], pr[6], pr[7]);
    o4[2] = make_float4(pr[8], pr[9], pr[10], pr[11]);
    if (dup) {
        float4* d4 = (float4*)(out + NPRED + base);
        d4[0] = make_float4(pr[0], pr[1], pr[2], pr[3]);
        d4[1] = make_float4(pr[4], pr[5], pr[6], pr[7]);
        d4[2] = make_float4(pr[8], pr[9], pr[10], pr[11]);
    }
}

extern "C" void kernel_launch(void* const* d_in, const int* in_sizes, int n_in,
                              void* d_out, int out_size) {
    Meta m;
    m.wz = (const float*)d_in[2];
    m.bz = (const float*)d_in[3];
    for (int g = 0; g < 6; g++) {   // rx, rh, zx, zh, cx, ch
        m.Wl[g] = (const float*)d_in[4 + g * 4];
        m.bl[g] = (const float*)d_in[5 + g * 4];
        m.Wb[g] = (const float*)d_in[6 + g * 4];
        m.bb[g] = (const float*)d_in[7 + g * 4];
    }
    m.Wo = (const float*)d_in[28];
    const float* x  = (const float*)d_in[0];
    const float* bo = (const float*)d_in[29];
    const float* Wp = (const float*)d_in[30];
    const float* bp = (const float*)d_in[31];
    float* out = (float*)d_out;

    pre_kernel<<<321, 256>>>(m);

    int dup = (out_size >= 2 * NPRED) ? 1 : 0;
    cudaFuncSetAttribute(gru_mma, cudaFuncAttributeMaxDynamicSharedMemorySize, SMEM_BYTES);
    gru_mma<<<1024, 128, SMEM_BYTES>>>(x, bo, Wp, bp, out, dup);
}

// round 9
// speedup vs baseline: 3.3022x; 1.1462x over previous
#include <cuda_runtime.h>
#include <cuda_bf16.h>
#include <stdint.h>

#define T_ 12
#define BN_TOT 131072
#define NPRED (BN_TOT * 12)

__device__ __align__(16) uint32_t g_Bh[T_ * 6144];
__device__ __align__(16) uint32_t g_Bl[T_ * 6144];
__device__ __align__(16) float g_epi[T_ * 64 * 12];

struct Meta { const float *wz, *bz, *Wl[6], *bl[6], *Wb[6], *bb[6], *Wo; };

__device__ __forceinline__ float dot32(const float* a, const float* b) {
    float s = 0.f;
#pragma unroll
    for (int m = 0; m < 32; m++) s = fmaf(a[m], b[m], s);
    return s;
}
__device__ __forceinline__ uint32_t pkbf(float a, float b) {
    return ((uint32_t)__bfloat16_as_ushort(__float2bfloat16(b)) << 16) |
           __bfloat16_as_ushort(__float2bfloat16(a));
}
// one-instruction pack: low half = a, high half = b
__device__ __forceinline__ uint32_t pk2(float a, float b) {
    uint32_t d;
    asm("cvt.rn.bf16x2.f32 %0, %1, %2;" : "=r"(d) : "f"(b), "f"(a));
    return d;
}
__device__ __forceinline__ float bflo(uint32_t w) {
    return __bfloat162float(__ushort_as_bfloat16((unsigned short)(w & 0xFFFF)));
}
__device__ __forceinline__ float bfhi(uint32_t w) {
    return __bfloat162float(__ushort_as_bfloat16((unsigned short)(w >> 16)));
}
__device__ __forceinline__ float tanh_ap(float x) {
    float y;
    asm("tanh.approx.f32 %0, %1;" : "=f"(y) : "f"(x));
    return y;
}

// B fragment-ready: word idx = t*6144 + (g*8+j)*256 + ks*64 + lane*2 + half
// word = {B[n,k0], B[n,k0+1]} bf16x2, n = nt*8 + lane/4, k0 = ks*16 + (lane%4)*2 + half*8
// r/z gate rows (g<2) are PRE-SCALED by 0.5 (sigmoid-via-tanh folding).
__global__ void pre_kernel(Meta p) {
    int idx = blockIdx.x * 256 + threadIdx.x;
    if (idx < 73728) {
        int t = idx / 6144, r = idx % 6144;
        int nt = r / 256, r2 = r % 256;
        int ks = r2 / 64, r3 = r2 % 64;
        int ln = r3 >> 1, half = r3 & 1;
        int n = nt * 8 + (ln >> 2);
        int k0 = ks * 16 + (ln & 3) * 2 + half * 8;
        int g = n >> 6, i = n & 63;
        float gs = (g < 2) ? 0.5f : 1.0f;
        const float* wzt = p.wz + t * 32;
        float s0 = gs * (dot32(wzt, p.Wl[2 * g + 1] + (i * 64 + k0) * 32) + p.bl[2 * g + 1][i * 64 + k0]);
        float s1 = gs * (dot32(wzt, p.Wl[2 * g + 1] + (i * 64 + k0 + 1) * 32) + p.bl[2 * g + 1][i * 64 + k0 + 1]);
        uint32_t wh = pkbf(s0, s1);
        g_Bh[idx] = wh;
        g_Bl[idx] = pkbf(s0 - bflo(wh), s1 - bfhi(wh));
    } else if (idx < 73728 + 8448) {
        int e = idx - 73728;
        int t = e / 704, r = e % 704;
        int i = r / 11, s2 = r % 11;
        float v;
        if (s2 < 6) {
            int g = s2 >> 1, d = s2 & 1;
            v = dot32(p.wz + t * 32, p.Wl[2 * g] + (i * 2 + d) * 32) + p.bl[2 * g][i * 2 + d];
            if (g < 2) v *= 0.5f;     // fold sigmoid /2 into r/z x-coeffs
        } else if (s2 == 6)
            v = 0.5f * (dot32(p.bz + t * 32, p.Wb[0] + i * 32) + p.bb[0][i]
                      + dot32(p.bz + t * 32, p.Wb[1] + i * 32) + p.bb[1][i]);
        else if (s2 == 7)
            v = 0.5f * (dot32(p.bz + t * 32, p.Wb[2] + i * 32) + p.bb[2][i]
                      + dot32(p.bz + t * 32, p.Wb[3] + i * 32) + p.bb[3][i]);
        else if (s2 == 8)
            v = dot32(p.bz + t * 32, p.Wb[4] + i * 32) + p.bb[4][i];
        else if (s2 == 9)
            v = dot32(p.bz + t * 32, p.Wb[5] + i * 32) + p.bb[5][i];
        else
            v = p.Wo[i];
        g_epi[(t * 64 + i) * 12 + s2] = v;
    }
}

#define MMA(d, a, b0_, b1_) \
    asm volatile("mma.sync.aligned.m16n8k16.row.col.f32.bf16.bf16.f32 " \
        "{%0,%1,%2,%3}, {%4,%5,%6,%7}, {%8,%9}, {%0,%1,%2,%3};" \
        : "+f"((d)[0]), "+f"((d)[1]), "+f"((d)[2]), "+f"((d)[3]) \
        : "r"((a)[0]), "r"((a)[1]), "r"((a)[2]), "r"((a)[3]), "r"(b0_), "r"(b1_))

#define SM_BH  0
#define SM_BL  24576
#define SM_X   49152
#define SM_SEQ 61952
#define SM_EPI 68096
#define SM_WP  71168
#define SM_BP  71744
#define SM_HF  71808
#define SMEM_BYTES (71808 + 32768)

// Epilogue per element (all gates via tanh.approx; /2 pre-folded for r/z):
//   tr = tanh(argr'); tz = tanh(argz')
//   argc = xcb + 0.5*(1+tr)*(dc+bch);  c = tanh(argc)
//   hn = 0.5*((hold+c) + tz*(hold-c))
// h staged fp32 in sHf[e][tid] (e = element 0..63); A fragments rebuilt once/step.
__global__ void __launch_bounds__(128, 2)
gru_mma(const float* __restrict__ x, const float* __restrict__ bo,
        const float* __restrict__ Wp, const float* __restrict__ bp,
        float* __restrict__ out, int dup)
{
    extern __shared__ char smem[];
    const int tid = threadIdx.x, lane = tid & 31, wid = tid >> 5;
    const int bn0 = blockIdx.x * 128;
    const int g4 = lane >> 2, q2 = (lane & 3) * 2;

    float* sx = (float*)(smem + SM_X);
    float* sSeq = (float*)(smem + SM_SEQ);
    float* sHf = (float*)(smem + SM_HF);   // [64 elements][128 tid], fp32 h
    if (tid < 12) ((float*)(smem + SM_BP))[tid] = bp[tid];
    for (int k = tid; k < 144; k += 128) ((float*)(smem + SM_WP))[k] = Wp[k];
    {
        const float4* gx = (const float4*)x + (size_t)(bn0 + tid) * 6;
#pragma unroll
        for (int u = 0; u < 6; u++) {
            float4 v = gx[u];
            sx[tid * 25 + 4 * u] = v.x; sx[tid * 25 + 4 * u + 1] = v.y;
            sx[tid * 25 + 4 * u + 2] = v.z; sx[tid * 25 + 4 * u + 3] = v.w;
        }
    }
#pragma unroll
    for (int e = 0; e < 64; e++) sHf[e * 128 + tid] = 0.f;

    uint32_t Ah[2][4][4], Al[2][4][4];
#pragma unroll
    for (int a = 0; a < 2; a++)
#pragma unroll
        for (int b = 0; b < 4; b++)
#pragma unroll
            for (int c = 0; c < 4; c++) { Ah[a][b][c] = 0u; Al[a][b][c] = 0u; }
    const float bo0 = __ldg(bo);

    for (int t = 0; t < T_; t++) {
        __syncthreads();
        {
            const uint4* gb = (const uint4*)(g_Bh + t * 6144);
            const uint4* gl = (const uint4*)(g_Bl + t * 6144);
            uint4* db = (uint4*)(smem + SM_BH);
            uint4* dl = (uint4*)(smem + SM_BL);
#pragma unroll
            for (int k = 0; k < 12; k++) {
                db[k * 128 + tid] = gb[k * 128 + tid];
                dl[k * 128 + tid] = gl[k * 128 + tid];
            }
            const uint4* ge = (const uint4*)(g_epi + t * 768);
            uint4* de = (uint4*)(smem + SM_EPI);
            de[tid] = ge[tid];
            if (tid < 64) de[128 + tid] = ge[128 + tid];
        }
        __syncthreads();

        float x0[4], x1[4], oacc[4];
#pragma unroll
        for (int rr = 0; rr < 4; rr++) {
            int row = wid * 32 + g4 + rr * 8;
            x0[rr] = sx[row * 25 + 2 * t];
            x1[rr] = sx[row * 25 + 2 * t + 1];
            oacc[rr] = 0.f;
        }
        const uint32_t* sBh = (const uint32_t*)(smem + SM_BH);
        const uint32_t* sBl = (const uint32_t*)(smem + SM_BL);
        const float4* sE = (const float4*)(smem + SM_EPI);

#pragma unroll
        for (int j = 0; j < 8; j++) {
            float d[3][2][4];
#pragma unroll
            for (int a = 0; a < 3; a++)
#pragma unroll
                for (int b = 0; b < 2; b++)
#pragma unroll
                    for (int c = 0; c < 4; c++) d[a][b][c] = 0.f;
#pragma unroll
            for (int ks = 0; ks < 4; ks++) {
#pragma unroll
                for (int g3 = 0; g3 < 3; g3++) {
                    int bi = ((g3 * 8 + j) * 4 + ks) * 64 + lane * 2;
                    uint32_t bh0 = sBh[bi], bh1 = sBh[bi + 1];
                    uint32_t bl0 = sBl[bi], bl1 = sBl[bi + 1];
#pragma unroll
                    for (int mt = 0; mt < 2; mt++) {
                        MMA(d[g3][mt], Ah[mt][ks], bh0, bh1);
                        MMA(d[g3][mt], Al[mt][ks], bh0, bh1);
                        MMA(d[g3][mt], Ah[mt][ks], bl0, bl1);
                    }
                }
            }
            int i0 = j * 8 + q2;
            float4 e0a = sE[i0 * 3], e1a = sE[i0 * 3 + 1], e2a = sE[i0 * 3 + 2];
            float4 e0b = sE[i0 * 3 + 3], e1b = sE[i0 * 3 + 4], e2b = sE[i0 * 3 + 5];
            int ks = j >> 1, rb = (j & 1) * 2;
#pragma unroll
            for (int mt = 0; mt < 2; mt++) {
#pragma unroll
                for (int pp = 0; pp < 2; pp++) {
                    int rr = mt * 2 + pp;
                    int w = (mt * 4 + ks) * 4 + rb + pp;
                    float hold0 = sHf[(2 * w) * 128 + tid];
                    float hold1 = sHf[(2 * w + 1) * 128 + tid];
                    float dr0 = d[0][mt][pp * 2], dr1 = d[0][mt][pp * 2 + 1];
                    float dz0 = d[1][mt][pp * 2], dz1 = d[1][mt][pp * 2 + 1];
                    float dc0 = d[2][mt][pp * 2], dc1 = d[2][mt][pp * 2 + 1];

                    float tr0 = tanh_ap(dr0 + x0[rr] * e0a.x + x1[rr] * e0a.y + e1a.z);
                    float tz0 = tanh_ap(dz0 + x0[rr] * e0a.z + x1[rr] * e0a.w + e1a.w);
                    float u0 = dc0 + e2a.y;
                    float xcb0 = x0[rr] * e1a.x + x1[rr] * e1a.y + e2a.x;
                    float c0 = tanh_ap(fmaf(0.5f, fmaf(tr0, u0, u0), xcb0));
                    float hn0 = 0.5f * fmaf(tz0, hold0 - c0, hold0 + c0);

                    float tr1 = tanh_ap(dr1 + x0[rr] * e0b.x + x1[rr] * e0b.y + e1b.z);
                    float tz1 = tanh_ap(dz1 + x0[rr] * e0b.z + x1[rr] * e0b.w + e1b.w);
                    float u1 = dc1 + e2b.y;
                    float xcb1 = x0[rr] * e1b.x + x1[rr] * e1b.y + e2b.x;
                    float c1 = tanh_ap(fmaf(0.5f, fmaf(tr1, u1, u1), xcb1));
                    float hn1 = 0.5f * fmaf(tz1, hold1 - c1, hold1 + c1);

                    oacc[rr] = fmaf(hn0, e2a.z, oacc[rr]);
                    oacc[rr] = fmaf(hn1, e2b.z, oacc[rr]);
                    sHf[(2 * w) * 128 + tid] = hn0;
                    sHf[(2 * w + 1) * 128 + tid] = hn1;
                }
            }
        }
        // all MMAs of step t done -> rebuild A fragments from fp32 h (bf16 split)
#pragma unroll
        for (int mt = 0; mt < 2; mt++)
#pragma unroll
            for (int ks = 0; ks < 4; ks++)
#pragma unroll
                for (int c = 0; c < 4; c++) {
                    int w = (mt * 4 + ks) * 4 + c;
                    float f0 = sHf[(2 * w) * 128 + tid];
                    float f1 = sHf[(2 * w + 1) * 128 + tid];
                    uint32_t nh = pk2(f0, f1);
                    Ah[mt][ks][c] = nh;
                    Al[mt][ks][c] = pk2(f0 - bflo(nh), f1 - bfhi(nh));
                }
#pragma unroll
        for (int rr = 0; rr < 4; rr++) {
            float v = oacc[rr];
            v += __shfl_xor_sync(0xffffffffu, v, 1);
            v += __shfl_xor_sync(0xffffffffu, v, 2);
            v = fmaxf(v + bo0, 0.f);
            sSeq[t * 128 + wid * 32 + g4 + rr * 8] = v;  // quad lanes write same value
        }
    }
    __syncthreads();

    const float* sWp = (const float*)(smem + SM_WP);
    const float* sbp = (const float*)(smem + SM_BP);
    float sq[12];
#pragma unroll
    for (int tt = 0; tt < 12; tt++) sq[tt] = sSeq[tt * 128 + tid];
    float pr[12];
#pragma unroll
    for (int p = 0; p < 12; p++) {
        float a = sbp[p];
#pragma unroll
        for (int tt = 0; tt < 12; tt++) a = fmaf(sq[tt], sWp[p * 12 + tt], a);
        pr[p] = a;
    }
    size_t base = (size_t)(bn0 + tid) * 12;
    float4* o4 = (float4*)(out + base);
    o4[0] = make_float4(pr[0], pr[1], pr[2], pr[3]);
    o4[1] = make_float4(pr[4], pr[5], pr[6], pr[7]);
    o4[2] = make_float4(pr[8], pr[9], pr[10], pr[11]);
    if (dup) {
        float4* d4 = (float4*)(out + NPRED + base);
        d4[0] = make_float4(pr[0], pr[1], pr[2], pr[3]);
        d4[1] = make_float4(pr[4], pr[5], pr[6], pr[7]);
        d4[2] = make_float4(pr[8], pr[9], pr[10], pr[11]);
    }
}

extern "C" void kernel_launch(void* const* d_in, const int* in_sizes, int n_in,
                              void* d_out, int out_size) {
    Meta m;
    m.wz = (const float*)d_in[2];
    m.bz = (const float*)d_in[3];
    for (int g = 0; g < 6; g++) {   // rx, rh, zx, zh, cx, ch
        m.Wl[g] = (const float*)d_in[4 + g * 4];
        m.bl[g] = (const float*)d_in[5 + g * 4];
        m.Wb[g] = (const float*)d_in[6 + g * 4];
        m.bb[g] = (const float*)d_in[7 + g * 4];
    }
    m.Wo = (const float*)d_in[28];
    const float* x  = (const float*)d_in[0];
    const float* bo = (const float*)d_in[29];
    const float* Wp = (const float*)d_in[30];
    const float* bp = (const float*)d_in[31];
    float* out = (float*)d_out;

    pre_kernel<<<321, 256>>>(m);

    int dup = (out_size >= 2 * NPRED) ? 1 : 0;
    cudaFuncSetAttribute(gru_mma, cudaFuncAttributeMaxDynamicSharedMemorySize, SMEM_BYTES);
    gru_mma<<<1024, 128, SMEM_BYTES>>>(x, bo, Wp, bp, out, dup);
}

// round 10
// speedup vs baseline: 4.3310x; 1.3115x over previous
#include <cuda_runtime.h>
#include <cuda_bf16.h>
#include <stdint.h>

#define T_ 12
#define BN_TOT 131072
#define NPRED (BN_TOT * 12)

__device__ __align__(16) uint32_t g_Bh[T_ * 6144];
__device__ __align__(16) float g_epi[T_ * 64 * 12];

struct Meta { const float *wz, *bz, *Wl[6], *bl[6], *Wb[6], *bb[6], *Wo; };

__device__ __forceinline__ float dot32(const float* a, const float* b) {
    float s = 0.f;
#pragma unroll
    for (int m = 0; m < 32; m++) s = fmaf(a[m], b[m], s);
    return s;
}
__device__ __forceinline__ uint32_t pkbf(float a, float b) {
    return ((uint32_t)__bfloat16_as_ushort(__float2bfloat16(b)) << 16) |
           __bfloat16_as_ushort(__float2bfloat16(a));
}
// one-instruction pack: low half = a, high half = b
__device__ __forceinline__ uint32_t pk2(float a, float b) {
    uint32_t d;
    asm("cvt.rn.bf16x2.f32 %0, %1, %2;" : "=r"(d) : "f"(b), "f"(a));
    return d;
}
__device__ __forceinline__ float bflo(uint32_t w) {
    return __bfloat162float(__ushort_as_bfloat16((unsigned short)(w & 0xFFFF)));
}
__device__ __forceinline__ float bfhi(uint32_t w) {
    return __bfloat162float(__ushort_as_bfloat16((unsigned short)(w >> 16)));
}
__device__ __forceinline__ float tanh_ap(float x) {
    float y;
    asm("tanh.approx.f32 %0, %1;" : "=f"(y) : "f"(x));
    return y;
}

// B fragment-ready (bf16, single precision level): word idx = t*6144 + (g*8+j)*256 + ks*64 + lane*2 + half
// word = {B[n,k0], B[n,k0+1]} bf16x2, n = nt*8 + lane/4, k0 = ks*16 + (lane%4)*2 + half*8
// r/z gate rows (g<2) are PRE-SCALED by 0.5 (sigmoid-via-tanh folding).
__global__ void pre_kernel(Meta p) {
    int idx = blockIdx.x * 256 + threadIdx.x;
    if (idx < 73728) {
        int t = idx / 6144, r = idx % 6144;
        int nt = r / 256, r2 = r % 256;
        int ks = r2 / 64, r3 = r2 % 64;
        int ln = r3 >> 1, half = r3 & 1;
        int n = nt * 8 + (ln >> 2);
        int k0 = ks * 16 + (ln & 3) * 2 + half * 8;
        int g = n >> 6, i = n & 63;
        float gs = (g < 2) ? 0.5f : 1.0f;
        const float* wzt = p.wz + t * 32;
        float s0 = gs * (dot32(wzt, p.Wl[2 * g + 1] + (i * 64 + k0) * 32) + p.bl[2 * g + 1][i * 64 + k0]);
        float s1 = gs * (dot32(wzt, p.Wl[2 * g + 1] + (i * 64 + k0 + 1) * 32) + p.bl[2 * g + 1][i * 64 + k0 + 1]);
        g_Bh[idx] = pkbf(s0, s1);
    } else if (idx < 73728 + 8448) {
        int e = idx - 73728;
        int t = e / 704, r = e % 704;
        int i = r / 11, s2 = r % 11;
        float v;
        if (s2 < 6) {
            int g = s2 >> 1, d = s2 & 1;
            v = dot32(p.wz + t * 32, p.Wl[2 * g] + (i * 2 + d) * 32) + p.bl[2 * g][i * 2 + d];
            if (g < 2) v *= 0.5f;     // fold sigmoid /2 into r/z x-coeffs
        } else if (s2 == 6)
            v = 0.5f * (dot32(p.bz + t * 32, p.Wb[0] + i * 32) + p.bb[0][i]
                      + dot32(p.bz + t * 32, p.Wb[1] + i * 32) + p.bb[1][i]);
        else if (s2 == 7)
            v = 0.5f * (dot32(p.bz + t * 32, p.Wb[2] + i * 32) + p.bb[2][i]
                      + dot32(p.bz + t * 32, p.Wb[3] + i * 32) + p.bb[3][i]);
        else if (s2 == 8)
            v = dot32(p.bz + t * 32, p.Wb[4] + i * 32) + p.bb[4][i];
        else if (s2 == 9)
            v = dot32(p.bz + t * 32, p.Wb[5] + i * 32) + p.bb[5][i];
        else
            v = p.Wo[i];
        g_epi[(t * 64 + i) * 12 + s2] = v;
    }
}

#define MMA(d, a, b0_, b1_) \
    asm volatile("mma.sync.aligned.m16n8k16.row.col.f32.bf16.bf16.f32 " \
        "{%0,%1,%2,%3}, {%4,%5,%6,%7}, {%8,%9}, {%0,%1,%2,%3};" \
        : "+f"((d)[0]), "+f"((d)[1]), "+f"((d)[2]), "+f"((d)[3]) \
        : "r"((a)[0]), "r"((a)[1]), "r"((a)[2]), "r"((a)[3]), "r"(b0_), "r"(b1_))

// double-buffered B + epi; sHf column-private
#define SM_BH0  0
#define SM_BH1  24576
#define SM_X    49152
#define SM_SEQ  61952
#define SM_EPI0 68096
#define SM_EPI1 71168
#define SM_WP   74240
#define SM_BP   74816
#define SM_HF   74880
#define SMEM_BYTES (74880 + 32768)

// Epilogue per element (all gates via tanh.approx; /2 pre-folded for r/z):
//   tr = tanh(argr'); tz = tanh(argz')
//   argc = xcb + 0.5*(1+tr)*(dc+bch);  c = tanh(argc)
//   hn = 0.5*((hold+c) + tz*(hold-c))
__global__ void __launch_bounds__(128, 2)
gru_mma(const float* __restrict__ x, const float* __restrict__ bo,
        const float* __restrict__ Wp, const float* __restrict__ bp,
        float* __restrict__ out, int dup)
{
    extern __shared__ char smem[];
    const int tid = threadIdx.x, lane = tid & 31, wid = tid >> 5;
    const int bn0 = blockIdx.x * 128;
    const int g4 = lane >> 2, q2 = (lane & 3) * 2;

    float* sx = (float*)(smem + SM_X);
    float* sSeq = (float*)(smem + SM_SEQ);
    float* sHf = (float*)(smem + SM_HF);   // [64 elements][128 tid], fp32 h
    if (tid < 12) ((float*)(smem + SM_BP))[tid] = bp[tid];
    for (int k = tid; k < 144; k += 128) ((float*)(smem + SM_WP))[k] = Wp[k];
    {
        const float4* gx = (const float4*)x + (size_t)(bn0 + tid) * 6;
#pragma unroll
        for (int u = 0; u < 6; u++) {
            float4 v = gx[u];
            sx[tid * 25 + 4 * u] = v.x; sx[tid * 25 + 4 * u + 1] = v.y;
            sx[tid * 25 + 4 * u + 2] = v.z; sx[tid * 25 + 4 * u + 3] = v.w;
        }
    }
#pragma unroll
    for (int e = 0; e < 64; e++) sHf[e * 128 + tid] = 0.f;
    {   // prologue: stage t=0 into buffer 0
        const uint4* gb = (const uint4*)(g_Bh);
        uint4* db = (uint4*)(smem + SM_BH0);
#pragma unroll
        for (int k = 0; k < 12; k++) db[k * 128 + tid] = gb[k * 128 + tid];
        const uint4* ge = (const uint4*)(g_epi);
        uint4* de = (uint4*)(smem + SM_EPI0);
        de[tid] = ge[tid];
        if (tid < 64) de[128 + tid] = ge[128 + tid];
    }

    uint32_t Ah[2][4][4], Al[2][4][4];
#pragma unroll
    for (int a = 0; a < 2; a++)
#pragma unroll
        for (int b = 0; b < 4; b++)
#pragma unroll
            for (int c = 0; c < 4; c++) { Ah[a][b][c] = 0u; Al[a][b][c] = 0u; }
    const float bo0 = __ldg(bo);
    __syncthreads();

    for (int t = 0; t < T_; t++) {
        const uint32_t* sBh = (const uint32_t*)(smem + ((t & 1) ? SM_BH1 : SM_BH0));
        const float4* sE = (const float4*)(smem + ((t & 1) ? SM_EPI1 : SM_EPI0));

        // stage next step into the other buffer (overlaps with this step's work)
        if (t + 1 < T_) {
            const uint4* gb = (const uint4*)(g_Bh + (t + 1) * 6144);
            uint4* db = (uint4*)(smem + (((t + 1) & 1) ? SM_BH1 : SM_BH0));
#pragma unroll
            for (int k = 0; k < 12; k++) db[k * 128 + tid] = gb[k * 128 + tid];
            const uint4* ge = (const uint4*)(g_epi + (t + 1) * 768);
            uint4* de = (uint4*)(smem + (((t + 1) & 1) ? SM_EPI1 : SM_EPI0));
            de[tid] = ge[tid];
            if (tid < 64) de[128 + tid] = ge[128 + tid];
        }

        float x0[4], x1[4], oacc[4];
#pragma unroll
        for (int rr = 0; rr < 4; rr++) {
            int row = wid * 32 + g4 + rr * 8;
            x0[rr] = sx[row * 25 + 2 * t];
            x1[rr] = sx[row * 25 + 2 * t + 1];
            oacc[rr] = 0.f;
        }

#pragma unroll
        for (int j = 0; j < 8; j++) {
            float d[3][2][4];
#pragma unroll
            for (int a = 0; a < 3; a++)
#pragma unroll
                for (int b = 0; b < 2; b++)
#pragma unroll
                    for (int c = 0; c < 4; c++) d[a][b][c] = 0.f;
#pragma unroll
            for (int ks = 0; ks < 4; ks++) {
#pragma unroll
                for (int g3 = 0; g3 < 3; g3++) {
                    int bi = ((g3 * 8 + j) * 4 + ks) * 64 + lane * 2;
                    uint32_t bh0 = sBh[bi], bh1 = sBh[bi + 1];
#pragma unroll
                    for (int mt = 0; mt < 2; mt++) {
                        MMA(d[g3][mt], Ah[mt][ks], bh0, bh1);
                        MMA(d[g3][mt], Al[mt][ks], bh0, bh1);
                    }
                }
            }
            int i0 = j * 8 + q2;
            float4 e0a = sE[i0 * 3], e1a = sE[i0 * 3 + 1], e2a = sE[i0 * 3 + 2];
            float4 e0b = sE[i0 * 3 + 3], e1b = sE[i0 * 3 + 4], e2b = sE[i0 * 3 + 5];
            int ks = j >> 1, rb = (j & 1) * 2;
#pragma unroll
            for (int mt = 0; mt < 2; mt++) {
#pragma unroll
                for (int pp = 0; pp < 2; pp++) {
                    int rr = mt * 2 + pp;
                    int w = (mt * 4 + ks) * 4 + rb + pp;
                    float hold0 = sHf[(2 * w) * 128 + tid];
                    float hold1 = sHf[(2 * w + 1) * 128 + tid];
                    float dr0 = d[0][mt][pp * 2], dr1 = d[0][mt][pp * 2 + 1];
                    float dz0 = d[1][mt][pp * 2], dz1 = d[1][mt][pp * 2 + 1];
                    float dc0 = d[2][mt][pp * 2], dc1 = d[2][mt][pp * 2 + 1];

                    float tr0 = tanh_ap(dr0 + x0[rr] * e0a.x + x1[rr] * e0a.y + e1a.z);
                    float tz0 = tanh_ap(dz0 + x0[rr] * e0a.z + x1[rr] * e0a.w + e1a.w);
                    float u0 = dc0 + e2a.y;
                    float xcb0 = x0[rr] * e1a.x + x1[rr] * e1a.y + e2a.x;
                    float c0 = tanh_ap(fmaf(0.5f, fmaf(tr0, u0, u0), xcb0));
                    float hn0 = 0.5f * fmaf(tz0, hold0 - c0, hold0 + c0);

                    float tr1 = tanh_ap(dr1 + x0[rr] * e0b.x + x1[rr] * e0b.y + e1b.z);
                    float tz1 = tanh_ap(dz1 + x0[rr] * e0b.z + x1[rr] * e0b.w + e1b.w);
                    float u1 = dc1 + e2b.y;
                    float xcb1 = x0[rr] * e1b.x + x1[rr] * e1b.y + e2b.x;
                    float c1 = tanh_ap(fmaf(0.5f, fmaf(tr1, u1, u1), xcb1));
                    float hn1 = 0.5f * fmaf(tz1, hold1 - c1, hold1 + c1);

                    oacc[rr] = fmaf(hn0, e2a.z, oacc[rr]);
                    oacc[rr] = fmaf(hn1, e2b.z, oacc[rr]);
                    sHf[(2 * w) * 128 + tid] = hn0;
                    sHf[(2 * w + 1) * 128 + tid] = hn1;
                }
            }
        }
        // all MMAs of step t done -> rebuild A fragments from fp32 h (bf16 split)
#pragma unroll
        for (int mt = 0; mt < 2; mt++)
#pragma unroll
            for (int ks = 0; ks < 4; ks++)
#pragma unroll
                for (int c = 0; c < 4; c++) {
                    int w = (mt * 4 + ks) * 4 + c;
                    float f0 = sHf[(2 * w) * 128 + tid];
                    float f1 = sHf[(2 * w + 1) * 128 + tid];
                    uint32_t nh = pk2(f0, f1);
                    Ah[mt][ks][c] = nh;
                    Al[mt][ks][c] = pk2(f0 - bflo(nh), f1 - bfhi(nh));
                }
#pragma unroll
        for (int rr = 0; rr < 4; rr++) {
            float v = oacc[rr];
            v += __shfl_xor_sync(0xffffffffu, v, 1);
            v += __shfl_xor_sync(0xffffffffu, v, 2);
            v = fmaxf(v + bo0, 0.f);
            sSeq[t * 128 + wid * 32 + g4 + rr * 8] = v;  // quad lanes write same value
        }
        // one barrier per step: staging of t+1 complete + reads of buf[t&1] done
        __syncthreads();
    }

    const float* sWp = (const float*)(smem + SM_WP);
    const float* sbp = (const float*)(smem + SM_BP);
    float sq[12];
#pragma unroll
    for (int tt = 0; tt < 12; tt++) sq[tt] = sSeq[tt * 128 + tid];
    float pr[12];
#pragma unroll
    for (int p = 0; p < 12; p++) {
        float a = sbp[p];
#pragma unroll
        for (int tt = 0; tt < 12; tt++) a = fmaf(sq[tt], sWp[p * 12 + tt], a);
        pr[p] = a;
    }
    size_t base = (size_t)(bn0 + tid) * 12;
    float4* o4 = (float4*)(out + base);
    o4[0] = make_float4(pr[0], pr[1], pr[2], pr[3]);
    o4[1] = make_float4(pr[4], pr[5], pr[6], pr[7]);
    o4[2] = make_float4(pr[8], pr[9], pr[10], pr[11]);
    if (dup) {
        float4* d4 = (float4*)(out + NPRED + base);
        d4[0] = make_float4(pr[0], pr[1], pr[2], pr[3]);
        d4[1] = make_float4(pr[4], pr[5], pr[6], pr[7]);
        d4[2] = make_float4(pr[8], pr[9], pr[10], pr[11]);
    }
}

extern "C" void kernel_launch(void* const* d_in, const int* in_sizes, int n_in,
                              void* d_out, int out_size) {
    Meta m;
    m.wz = (const float*)d_in[2];
    m.bz = (const float*)d_in[3];
    for (int g = 0; g < 6; g++) {   // rx, rh, zx, zh, cx, ch
        m.Wl[g] = (const float*)d_in[4 + g * 4];
        m.bl[g] = (const float*)d_in[5 + g * 4];
        m.Wb[g] = (const float*)d_in[6 + g * 4];
        m.bb[g] = (const float*)d_in[7 + g * 4];
    }
    m.Wo = (const float*)d_in[28];
    const float* x  = (const float*)d_in[0];
    const float* bo = (const float*)d_in[29];
    const float* Wp = (const float*)d_in[30];
    const float* bp = (const float*)d_in[31];
    float* out = (float*)d_out;

    pre_kernel<<<321, 256>>>(m);

    int dup = (out_size >= 2 * NPRED) ? 1 : 0;
    cudaFuncSetAttribute(gru_mma, cudaFuncAttributeMaxDynamicSharedMemorySize, SMEM_BYTES);
    gru_mma<<<1024, 128, SMEM_BYTES>>>(x, bo, Wp, bp, out, dup);
}

// round 11
// speedup vs baseline: 5.1500x; 1.1891x over previous
#include <cuda_runtime.h>
#include <cuda_bf16.h>
#include <stdint.h>

#define T_ 12
#define BN_TOT 131072
#define NPRED (BN_TOT * 12)

__device__ __align__(16) uint32_t g_Bh[T_ * 6144];
__device__ __align__(16) float g_epi[T_ * 64 * 12];

struct Meta { const float *wz, *bz, *Wl[6], *bl[6], *Wb[6], *bb[6], *Wo; };

__device__ __forceinline__ float dot32(const float* a, const float* b) {
    float s = 0.f;
#pragma unroll
    for (int m = 0; m < 32; m++) s = fmaf(a[m], b[m], s);
    return s;
}
__device__ __forceinline__ uint32_t pkbf(float a, float b) {
    return ((uint32_t)__bfloat16_as_ushort(__float2bfloat16(b)) << 16) |
           __bfloat16_as_ushort(__float2bfloat16(a));
}
// one-instruction pack: low half = a, high half = b
__device__ __forceinline__ uint32_t pk2(float a, float b) {
    uint32_t d;
    asm("cvt.rn.bf16x2.f32 %0, %1, %2;" : "=r"(d) : "f"(b), "f"(a));
    return d;
}
__device__ __forceinline__ float tanh_ap(float x) {
    float y;
    asm("tanh.approx.f32 %0, %1;" : "=f"(y) : "f"(x));
    return y;
}

// B fragment-ready (bf16): word idx = t*6144 + (g*8+j)*256 + ks*64 + lane*2 + half
// word = {B[n,k0], B[n,k0+1]} bf16x2, n = nt*8 + lane/4, k0 = ks*16 + (lane%4)*2 + half*8
// r/z gate rows (g<2) are PRE-SCALED by 0.5 (sigmoid-via-tanh folding).
__global__ void pre_kernel(Meta p) {
    int idx = blockIdx.x * 256 + threadIdx.x;
    if (idx < 73728) {
        int t = idx / 6144, r = idx % 6144;
        int nt = r / 256, r2 = r % 256;
        int ks = r2 / 64, r3 = r2 % 64;
        int ln = r3 >> 1, half = r3 & 1;
        int n = nt * 8 + (ln >> 2);
        int k0 = ks * 16 + (ln & 3) * 2 + half * 8;
        int g = n >> 6, i = n & 63;
        float gs = (g < 2) ? 0.5f : 1.0f;
        const float* wzt = p.wz + t * 32;
        float s0 = gs * (dot32(wzt, p.Wl[2 * g + 1] + (i * 64 + k0) * 32) + p.bl[2 * g + 1][i * 64 + k0]);
        float s1 = gs * (dot32(wzt, p.Wl[2 * g + 1] + (i * 64 + k0 + 1) * 32) + p.bl[2 * g + 1][i * 64 + k0 + 1]);
        g_Bh[idx] = pkbf(s0, s1);
    } else if (idx < 73728 + 8448) {
        int e = idx - 73728;
        int t = e / 704, r = e % 704;
        int i = r / 11, s2 = r % 11;
        float v;
        if (s2 < 6) {
            int g = s2 >> 1, d = s2 & 1;
            v = dot32(p.wz + t * 32, p.Wl[2 * g] + (i * 2 + d) * 32) + p.bl[2 * g][i * 2 + d];
            if (g < 2) v *= 0.5f;     // fold sigmoid /2 into r/z x-coeffs
        } else if (s2 == 6)
            v = 0.5f * (dot32(p.bz + t * 32, p.Wb[0] + i * 32) + p.bb[0][i]
                      + dot32(p.bz + t * 32, p.Wb[1] + i * 32) + p.bb[1][i]);
        else if (s2 == 7)
            v = 0.5f * (dot32(p.bz + t * 32, p.Wb[2] + i * 32) + p.bb[2][i]
                      + dot32(p.bz + t * 32, p.Wb[3] + i * 32) + p.bb[3][i]);
        else if (s2 == 8)
            v = dot32(p.bz + t * 32, p.Wb[4] + i * 32) + p.bb[4][i];
        else if (s2 == 9)
            v = dot32(p.bz + t * 32, p.Wb[5] + i * 32) + p.bb[5][i];
        else
            v = p.Wo[i];
        g_epi[(t * 64 + i) * 12 + s2] = v;
    }
}

#define MMA(d, a, b0_, b1_) \
    asm volatile("mma.sync.aligned.m16n8k16.row.col.f32.bf16.bf16.f32 " \
        "{%0,%1,%2,%3}, {%4,%5,%6,%7}, {%8,%9}, {%0,%1,%2,%3};" \
        : "+f"((d)[0]), "+f"((d)[1]), "+f"((d)[2]), "+f"((d)[3]) \
        : "r"((a)[0]), "r"((a)[1]), "r"((a)[2]), "r"((a)[3]), "r"(b0_), "r"(b1_))

// double-buffered B + epi; sHf column-private
#define SM_BH0  0
#define SM_BH1  24576
#define SM_X    49152
#define SM_SEQ  61952
#define SM_EPI0 68096
#define SM_EPI1 71168
#define SM_WP   74240
#define SM_BP   74816
#define SM_HF   74880
#define SMEM_BYTES (74880 + 32768)

// Epilogue per element (all gates via tanh.approx; /2 pre-folded for r/z):
//   tr = tanh(argr'); tz = tanh(argz')
//   argc = xcb + 0.5*(1+tr)*(dc+bch);  c = tanh(argc)
//   hn = 0.5*((hold+c) + tz*(hold-c))
// fp32 master h lives in sHf; MMA sees bf16 copy (single-pass).
__global__ void __launch_bounds__(128, 2)
gru_mma(const float* __restrict__ x, const float* __restrict__ bo,
        const float* __restrict__ Wp, const float* __restrict__ bp,
        float* __restrict__ out, int dup)
{
    extern __shared__ char smem[];
    const int tid = threadIdx.x, lane = tid & 31, wid = tid >> 5;
    const int bn0 = blockIdx.x * 128;
    const int g4 = lane >> 2, q2 = (lane & 3) * 2;

    float* sx = (float*)(smem + SM_X);
    float* sSeq = (float*)(smem + SM_SEQ);
    float* sHf = (float*)(smem + SM_HF);   // [64 elements][128 tid], fp32 h
    if (tid < 12) ((float*)(smem + SM_BP))[tid] = bp[tid];
    for (int k = tid; k < 144; k += 128) ((float*)(smem + SM_WP))[k] = Wp[k];
    {
        const float4* gx = (const float4*)x + (size_t)(bn0 + tid) * 6;
#pragma unroll
        for (int u = 0; u < 6; u++) {
            float4 v = gx[u];
            sx[tid * 25 + 4 * u] = v.x; sx[tid * 25 + 4 * u + 1] = v.y;
            sx[tid * 25 + 4 * u + 2] = v.z; sx[tid * 25 + 4 * u + 3] = v.w;
        }
    }
#pragma unroll
    for (int e = 0; e < 64; e++) sHf[e * 128 + tid] = 0.f;
    {   // prologue: stage t=0 into buffer 0
        const uint4* gb = (const uint4*)(g_Bh);
        uint4* db = (uint4*)(smem + SM_BH0);
#pragma unroll
        for (int k = 0; k < 12; k++) db[k * 128 + tid] = gb[k * 128 + tid];
        const uint4* ge = (const uint4*)(g_epi);
        uint4* de = (uint4*)(smem + SM_EPI0);
        de[tid] = ge[tid];
        if (tid < 64) de[128 + tid] = ge[128 + tid];
    }

    uint32_t Ah[2][4][4];
#pragma unroll
    for (int a = 0; a < 2; a++)
#pragma unroll
        for (int b = 0; b < 4; b++)
#pragma unroll
            for (int c = 0; c < 4; c++) Ah[a][b][c] = 0u;
    const float bo0 = __ldg(bo);
    __syncthreads();

    for (int t = 0; t < T_; t++) {
        const uint32_t* sBh = (const uint32_t*)(smem + ((t & 1) ? SM_BH1 : SM_BH0));
        const float4* sE = (const float4*)(smem + ((t & 1) ? SM_EPI1 : SM_EPI0));

        // stage next step into the other buffer (overlaps with this step's work)
        if (t + 1 < T_) {
            const uint4* gb = (const uint4*)(g_Bh + (t + 1) * 6144);
            uint4* db = (uint4*)(smem + (((t + 1) & 1) ? SM_BH1 : SM_BH0));
#pragma unroll
            for (int k = 0; k < 12; k++) db[k * 128 + tid] = gb[k * 128 + tid];
            const uint4* ge = (const uint4*)(g_epi + (t + 1) * 768);
            uint4* de = (uint4*)(smem + (((t + 1) & 1) ? SM_EPI1 : SM_EPI0));
            de[tid] = ge[tid];
            if (tid < 64) de[128 + tid] = ge[128 + tid];
        }

        float x0[4], x1[4], oacc[4];
#pragma unroll
        for (int rr = 0; rr < 4; rr++) {
            int row = wid * 32 + g4 + rr * 8;
            x0[rr] = sx[row * 25 + 2 * t];
            x1[rr] = sx[row * 25 + 2 * t + 1];
            oacc[rr] = 0.f;
        }

#pragma unroll
        for (int j = 0; j < 8; j++) {
            float d[3][2][4];
#pragma unroll
            for (int a = 0; a < 3; a++)
#pragma unroll
                for (int b = 0; b < 2; b++)
#pragma unroll
                    for (int c = 0; c < 4; c++) d[a][b][c] = 0.f;
#pragma unroll
            for (int ks = 0; ks < 4; ks++) {
#pragma unroll
                for (int g3 = 0; g3 < 3; g3++) {
                    int bi = ((g3 * 8 + j) * 4 + ks) * 64 + lane * 2;
                    uint32_t bh0 = sBh[bi], bh1 = sBh[bi + 1];
#pragma unroll
                    for (int mt = 0; mt < 2; mt++)
                        MMA(d[g3][mt], Ah[mt][ks], bh0, bh1);
                }
            }
            int i0 = j * 8 + q2;
            float4 e0a = sE[i0 * 3], e1a = sE[i0 * 3 + 1], e2a = sE[i0 * 3 + 2];
            float4 e0b = sE[i0 * 3 + 3], e1b = sE[i0 * 3 + 4], e2b = sE[i0 * 3 + 5];
            int ks = j >> 1, rb = (j & 1) * 2;
#pragma unroll
            for (int mt = 0; mt < 2; mt++) {
#pragma unroll
                for (int pp = 0; pp < 2; pp++) {
                    int rr = mt * 2 + pp;
                    int w = (mt * 4 + ks) * 4 + rb + pp;
                    float hold0 = sHf[(2 * w) * 128 + tid];
                    float hold1 = sHf[(2 * w + 1) * 128 + tid];
                    float dr0 = d[0][mt][pp * 2], dr1 = d[0][mt][pp * 2 + 1];
                    float dz0 = d[1][mt][pp * 2], dz1 = d[1][mt][pp * 2 + 1];
                    float dc0 = d[2][mt][pp * 2], dc1 = d[2][mt][pp * 2 + 1];

                    float tr0 = tanh_ap(dr0 + x0[rr] * e0a.x + x1[rr] * e0a.y + e1a.z);
                    float tz0 = tanh_ap(dz0 + x0[rr] * e0a.z + x1[rr] * e0a.w + e1a.w);
                    float u0 = dc0 + e2a.y;
                    float xcb0 = x0[rr] * e1a.x + x1[rr] * e1a.y + e2a.x;
                    float c0 = tanh_ap(fmaf(0.5f, fmaf(tr0, u0, u0), xcb0));
                    float hn0 = 0.5f * fmaf(tz0, hold0 - c0, hold0 + c0);

                    float tr1 = tanh_ap(dr1 + x0[rr] * e0b.x + x1[rr] * e0b.y + e1b.z);
                    float tz1 = tanh_ap(dz1 + x0[rr] * e0b.z + x1[rr] * e0b.w + e1b.w);
                    float u1 = dc1 + e2b.y;
                    float xcb1 = x0[rr] * e1b.x + x1[rr] * e1b.y + e2b.x;
                    float c1 = tanh_ap(fmaf(0.5f, fmaf(tr1, u1, u1), xcb1));
                    float hn1 = 0.5f * fmaf(tz1, hold1 - c1, hold1 + c1);

                    oacc[rr] = fmaf(hn0, e2a.z, oacc[rr]);
                    oacc[rr] = fmaf(hn1, e2b.z, oacc[rr]);
                    sHf[(2 * w) * 128 + tid] = hn0;
                    sHf[(2 * w + 1) * 128 + tid] = hn1;
                }
            }
        }
        // all MMAs of step t done -> rebuild A fragments from fp32 h (bf16)
#pragma unroll
        for (int mt = 0; mt < 2; mt++)
#pragma unroll
            for (int ks = 0; ks < 4; ks++)
#pragma unroll
                for (int c = 0; c < 4; c++) {
                    int w = (mt * 4 + ks) * 4 + c;
                    Ah[mt][ks][c] = pk2(sHf[(2 * w) * 128 + tid],
                                        sHf[(2 * w + 1) * 128 + tid]);
                }
#pragma unroll
        for (int rr = 0; rr < 4; rr++) {
            float v = oacc[rr];
            v += __shfl_xor_sync(0xffffffffu, v, 1);
            v += __shfl_xor_sync(0xffffffffu, v, 2);
            v = fmaxf(v + bo0, 0.f);
            sSeq[t * 128 + wid * 32 + g4 + rr * 8] = v;  // quad lanes write same value
        }
        // one barrier per step: staging of t+1 complete + reads of buf[t&1] done
        __syncthreads();
    }

    const float* sWp = (const float*)(smem + SM_WP);
    const float* sbp = (const float*)(smem + SM_BP);
    float sq[12];
#pragma unroll
    for (int tt = 0; tt < 12; tt++) sq[tt] = sSeq[tt * 128 + tid];
    float pr[12];
#pragma unroll
    for (int p = 0; p < 12; p++) {
        float a = sbp[p];
#pragma unroll
        for (int tt = 0; tt < 12; tt++) a = fmaf(sq[tt], sWp[p * 12 + tt], a);
        pr[p] = a;
    }
    size_t base = (size_t)(bn0 + tid) * 12;
    float4* o4 = (float4*)(out + base);
    o4[0] = make_float4(pr[0], pr[1], pr[2], pr[3]);
    o4[1] = make_float4(pr[4], pr[5], pr[6], pr[7]);
    o4[2] = make_float4(pr[8], pr[9], pr[10], pr[11]);
    if (dup) {
        float4* d4 = (float4*)(out + NPRED + base);
        d4[0] = make_float4(pr[0], pr[1], pr[2], pr[3]);
        d4[1] = make_float4(pr[4], pr[5], pr[6], pr[7]);
        d4[2] = make_float4(pr[8], pr[9], pr[10], pr[11]);
    }
}

extern "C" void kernel_launch(void* const* d_in, const int* in_sizes, int n_in,
                              void* d_out, int out_size) {
    Meta m;
    m.wz = (const float*)d_in[2];
    m.bz = (const float*)d_in[3];
    for (int g = 0; g < 6; g++) {   // rx, rh, zx, zh, cx, ch
        m.Wl[g] = (const float*)d_in[4 + g * 4];
        m.bl[g] = (const float*)d_in[5 + g * 4];
        m.Wb[g] = (const float*)d_in[6 + g * 4];
        m.bb[g] = (const float*)d_in[7 + g * 4];
    }
    m.Wo = (const float*)d_in[28];
    const float* x  = (const float*)d_in[0];
    const float* bo = (const float*)d_in[29];
    const float* Wp = (const float*)d_in[30];
    const float* bp = (const float*)d_in[31];
    float* out = (float*)d_out;

    pre_kernel<<<321, 256>>>(m);

    int dup = (out_size >= 2 * NPRED) ? 1 : 0;
    cudaFuncSetAttribute(gru_mma, cudaFuncAttributeMaxDynamicSharedMemorySize, SMEM_BYTES);
    gru_mma<<<1024, 128, SMEM_BYTES>>>(x, bo, Wp, bp, out, dup);
}

// round 14
// speedup vs baseline: 5.8733x; 1.1405x over previous
#include <cuda_runtime.h>
#include <cuda_bf16.h>
#include <stdint.h>

#define T_ 12
#define BN_TOT 131072
#define NPRED (BN_TOT * 12)

__device__ __align__(16) uint32_t g_Bh[T_ * 6144];
__device__ __align__(16) uint32_t g_Bx[T_ * 1536];
__device__ __align__(16) float g_E2[T_ * 128];

struct Meta { const float *wz, *bz, *Wl[6], *bl[6], *Wb[6], *bb[6], *Wo; };

__device__ __forceinline__ float dot32(const float* a, const float* b) {
    float s = 0.f;
#pragma unroll
    for (int m = 0; m < 32; m++) s = fmaf(a[m], b[m], s);
    return s;
}
__device__ __forceinline__ uint32_t pkbf(float a, float b) {
    return ((uint32_t)__bfloat16_as_ushort(__float2bfloat16(b)) << 16) |
           __bfloat16_as_ushort(__float2bfloat16(a));
}
__device__ __forceinline__ uint32_t pk2(float a, float b) {
    uint32_t d;
    asm("cvt.rn.bf16x2.f32 %0, %1, %2;" : "=r"(d) : "f"(b), "f"(a));
    return d;
}
__device__ __forceinline__ float bf16f(float x) {
    return __bfloat162float(__float2bfloat16(x));
}
__device__ __forceinline__ float tanh_ap(float x) {
    float y;
    asm("tanh.approx.f32 %0, %1;" : "=f"(y) : "f"(x));
    return y;
}

// g_Bh: h-weight fragments (bf16, r/z pre-scaled 0.5): word = t*6144 + (g*8+j)*256 + ks*64 + lane*2 + half
// g_Bx: x/bias fragments: word = t*1536 + (g*8+j)*64 + lane (lanes 0..31 used; 32..63 zero); by lane%4:
//   q0: {wxhi0, wxhi1}   q1: {bias_hi, bias_lo}   q2: {wxhi0, wxhi1}   q3: {wxlo0, wxlo1}
//   (pairs with A = [xhi, 1/1, xlo, xhi] -> x*wx + bias effectively fp32-exact)
// g_E2: per (t,i): {bch, Wo}
__global__ void pre_kernel(Meta p) {
    int idx = blockIdx.x * 256 + threadIdx.x;
    if (idx < 73728) {
        int t = idx / 6144, r = idx % 6144;
        int nt = r / 256, r2 = r % 256;
        int ks = r2 / 64, r3 = r2 % 64;
        int ln = r3 >> 1, half = r3 & 1;
        int n = nt * 8 + (ln >> 2);
        int k0 = ks * 16 + (ln & 3) * 2 + half * 8;
        int g = n >> 6, i = n & 63;
        float gs = (g < 2) ? 0.5f : 1.0f;
        const float* wzt = p.wz + t * 32;
        float s0 = gs * (dot32(wzt, p.Wl[2 * g + 1] + (i * 64 + k0) * 32) + p.bl[2 * g + 1][i * 64 + k0]);
        float s1 = gs * (dot32(wzt, p.Wl[2 * g + 1] + (i * 64 + k0 + 1) * 32) + p.bl[2 * g + 1][i * 64 + k0 + 1]);
        g_Bh[idx] = pkbf(s0, s1);
    } else if (idx < 73728 + 18432) {
        int e = idx - 73728;
        int t = e / 1536, r = e % 1536;
        int g = r / 512, r2 = r % 512;
        int j = r2 / 64, ln = r2 % 64;
        uint32_t outw = 0u;
        if (ln < 32) {   // only lane-words 0..31 are read (b0 per lane); avoid OOB nn
            int q = ln & 3, nn = j * 8 + (ln >> 2);
            float gs = (g < 2) ? 0.5f : 1.0f;
            const float* wzt = p.wz + t * 32;
            if (q == 1) {
                float b;
                if (g == 0)
                    b = 0.5f * (dot32(p.bz + t * 32, p.Wb[0] + nn * 32) + p.bb[0][nn]
                              + dot32(p.bz + t * 32, p.Wb[1] + nn * 32) + p.bb[1][nn]);
                else if (g == 1)
                    b = 0.5f * (dot32(p.bz + t * 32, p.Wb[2] + nn * 32) + p.bb[2][nn]
                              + dot32(p.bz + t * 32, p.Wb[3] + nn * 32) + p.bb[3][nn]);
                else
                    b = dot32(p.bz + t * 32, p.Wb[4] + nn * 32) + p.bb[4][nn];
                outw = pkbf(b, b - bf16f(b));
            } else {
                float w0 = gs * (dot32(wzt, p.Wl[2 * g] + (nn * 2 + 0) * 32) + p.bl[2 * g][nn * 2 + 0]);
                float w1 = gs * (dot32(wzt, p.Wl[2 * g] + (nn * 2 + 1) * 32) + p.bl[2 * g][nn * 2 + 1]);
                if (q == 3) outw = pkbf(w0 - bf16f(w0), w1 - bf16f(w1));
                else        outw = pkbf(w0, w1);
            }
        }
        g_Bx[e] = outw;   // FIX: was g_Bx[idx] — OOB write + g_Bx left uninitialized
    } else if (idx < 73728 + 18432 + 768) {
        int e = idx - 73728 - 18432;
        int t = e / 64, i = e % 64;
        g_E2[t * 128 + i * 2]     = dot32(p.bz + t * 32, p.Wb[5] + i * 32) + p.bb[5][i];  // bch
        g_E2[t * 128 + i * 2 + 1] = p.Wo[i];
    }
}

#define MMA(d, a0_, a1_, a2_, a3_, b0_, b1_) \
    asm volatile("mma.sync.aligned.m16n8k16.row.col.f32.bf16.bf16.f32 " \
        "{%0,%1,%2,%3}, {%4,%5,%6,%7}, {%8,%9}, {%0,%1,%2,%3};" \
        : "+f"((d)[0]), "+f"((d)[1]), "+f"((d)[2]), "+f"((d)[3]) \
        : "r"(a0_), "r"(a1_), "r"(a2_), "r"(a3_), "r"(b0_), "r"(b1_))

#define SM_BH0 0
#define SM_BH1 24576
#define SM_BX0 49152
#define SM_BX1 55296
#define SM_X   61440
#define SM_SEQ 74240
#define SM_E20 80384
#define SM_E21 80896
#define SM_WP  81408
#define SM_BP  81984
#define SM_HF  82048
#define SMEM_BYTES (82048 + 32768)

__global__ void __launch_bounds__(128, 2)
gru_mma(const float* __restrict__ x, const float* __restrict__ bo,
        const float* __restrict__ Wp, const float* __restrict__ bp,
        float* __restrict__ out, int dup)
{
    extern __shared__ char smem[];
    const int tid = threadIdx.x, lane = tid & 31, wid = tid >> 5;
    const int bn0 = blockIdx.x * 128;
    const int g4 = lane >> 2, q = lane & 3, q2 = q * 2;

    float* sx = (float*)(smem + SM_X);
    float* sSeq = (float*)(smem + SM_SEQ);
    float* sHf = (float*)(smem + SM_HF);   // [64 elements][128 tid], fp32 master h
    if (tid < 12) ((float*)(smem + SM_BP))[tid] = bp[tid];
    for (int k = tid; k < 144; k += 128) ((float*)(smem + SM_WP))[k] = Wp[k];
    {
        const float4* gx = (const float4*)x + (size_t)(bn0 + tid) * 6;
#pragma unroll
        for (int u = 0; u < 6; u++) {
            float4 v = gx[u];
            sx[tid * 25 + 4 * u] = v.x; sx[tid * 25 + 4 * u + 1] = v.y;
            sx[tid * 25 + 4 * u + 2] = v.z; sx[tid * 25 + 4 * u + 3] = v.w;
        }
    }
#pragma unroll
    for (int e = 0; e < 64; e++) sHf[e * 128 + tid] = 0.f;
    {   // prologue: stage t=0 into buffer 0
        const uint4* gb = (const uint4*)(g_Bh);
        uint4* db = (uint4*)(smem + SM_BH0);
#pragma unroll
        for (int k = 0; k < 12; k++) db[k * 128 + tid] = gb[k * 128 + tid];
        const uint4* gbx = (const uint4*)(g_Bx);
        uint4* dbx = (uint4*)(smem + SM_BX0);
#pragma unroll
        for (int k = 0; k < 3; k++) dbx[k * 128 + tid] = gbx[k * 128 + tid];
        if (tid < 32) ((uint4*)(smem + SM_E20))[tid] = ((const uint4*)g_E2)[tid];
    }

    uint32_t Ah[2][4][4];
#pragma unroll
    for (int a = 0; a < 2; a++)
#pragma unroll
        for (int b = 0; b < 4; b++)
#pragma unroll
            for (int c = 0; c < 4; c++) Ah[a][b][c] = 0u;
    const float bo0 = __ldg(bo);
    __syncthreads();

    for (int t = 0; t < T_; t++) {
        const uint32_t* sBh = (const uint32_t*)(smem + ((t & 1) ? SM_BH1 : SM_BH0));
        const uint32_t* sBx = (const uint32_t*)(smem + ((t & 1) ? SM_BX1 : SM_BX0));
        const float4* sE2 = (const float4*)(smem + ((t & 1) ? SM_E21 : SM_E20));

        // stage next step into the other buffer (overlaps with this step's work)
        if (t + 1 < T_) {
            const uint4* gb = (const uint4*)(g_Bh + (t + 1) * 6144);
            uint4* db = (uint4*)(smem + (((t + 1) & 1) ? SM_BH1 : SM_BH0));
#pragma unroll
            for (int k = 0; k < 12; k++) db[k * 128 + tid] = gb[k * 128 + tid];
            const uint4* gbx = (const uint4*)(g_Bx + (t + 1) * 1536);
            uint4* dbx = (uint4*)(smem + (((t + 1) & 1) ? SM_BX1 : SM_BX0));
#pragma unroll
            for (int k = 0; k < 3; k++) dbx[k * 128 + tid] = gbx[k * 128 + tid];
            if (tid < 32)
                ((uint4*)(smem + (((t + 1) & 1) ? SM_E21 : SM_E20)))[tid] =
                    ((const uint4*)(g_E2 + (t + 1) * 128))[tid];
        }

        float oacc[4];
        uint32_t ax0[2], ax1[2];
        {   // build x/bias A fragments: [xhi, 1/1, xlo, xhi] by lane quad pos
            float x0[4], x1[4], xh0[4], xh1[4], xl0[4], xl1[4];
#pragma unroll
            for (int rr = 0; rr < 4; rr++) {
                int row = wid * 32 + g4 + rr * 8;
                x0[rr] = sx[row * 25 + 2 * t];
                x1[rr] = sx[row * 25 + 2 * t + 1];
                xh0[rr] = bf16f(x0[rr]); xl0[rr] = x0[rr] - xh0[rr];
                xh1[rr] = bf16f(x1[rr]); xl1[rr] = x1[rr] - xh1[rr];
                oacc[rr] = 0.f;
            }
#pragma unroll
            for (int mt = 0; mt < 2; mt++) {
                int m2 = mt * 2;
                if (q == 1) { ax0[mt] = 0x3F803F80u; ax1[mt] = 0x3F803F80u; }
                else if (q == 2) {
                    ax0[mt] = pk2(xl0[m2], xl1[m2]);
                    ax1[mt] = pk2(xl0[m2 + 1], xl1[m2 + 1]);
                } else {
                    ax0[mt] = pk2(xh0[m2], xh1[m2]);
                    ax1[mt] = pk2(xh0[m2 + 1], xh1[m2 + 1]);
                }
            }
        }

#pragma unroll
        for (int j = 0; j < 8; j++) {
            float d[3][2][4], dxc[2][4];
#pragma unroll
            for (int a = 0; a < 3; a++)
#pragma unroll
                for (int b = 0; b < 2; b++)
#pragma unroll
                    for (int c = 0; c < 4; c++) d[a][b][c] = 0.f;
#pragma unroll
            for (int b = 0; b < 2; b++)
#pragma unroll
                for (int c = 0; c < 4; c++) dxc[b][c] = 0.f;
#pragma unroll
            for (int ks = 0; ks < 4; ks++) {
#pragma unroll
                for (int g3 = 0; g3 < 3; g3++) {
                    int bi = ((g3 * 8 + j) * 4 + ks) * 64 + lane * 2;
                    uint2 bh = *(const uint2*)(sBh + bi);
#pragma unroll
                    for (int mt = 0; mt < 2; mt++)
                        MMA(d[g3][mt], Ah[mt][ks][0], Ah[mt][ks][1], Ah[mt][ks][2], Ah[mt][ks][3],
                            bh.x, bh.y);
                }
            }
            {   // x-part + bias MMAs (one per gate per mt)
                uint32_t bxr = sBx[(0 * 8 + j) * 64 + lane];
                uint32_t bxz = sBx[(1 * 8 + j) * 64 + lane];
                uint32_t bxc = sBx[(2 * 8 + j) * 64 + lane];
#pragma unroll
                for (int mt = 0; mt < 2; mt++) {
                    MMA(d[0][mt], ax0[mt], ax1[mt], 0u, 0u, bxr, 0u);
                    MMA(d[1][mt], ax0[mt], ax1[mt], 0u, 0u, bxz, 0u);
                    MMA(dxc[mt], ax0[mt], ax1[mt], 0u, 0u, bxc, 0u);
                }
            }
            int i0 = j * 8 + q2;
            float4 e4 = sE2[i0 >> 1];   // {bch(i0), wo(i0), bch(i0+1), wo(i0+1)}
            int ks = j >> 1, rb = (j & 1) * 2;
#pragma unroll
            for (int mt = 0; mt < 2; mt++) {
#pragma unroll
                for (int pp = 0; pp < 2; pp++) {
                    int rr = mt * 2 + pp;
                    int w = (mt * 4 + ks) * 4 + rb + pp;
                    float hold0 = sHf[(2 * w) * 128 + tid];
                    float hold1 = sHf[(2 * w + 1) * 128 + tid];

                    float tr0 = tanh_ap(d[0][mt][pp * 2]);
                    float tz0 = tanh_ap(d[1][mt][pp * 2]);
                    float u0 = d[2][mt][pp * 2] + e4.x;
                    float c0 = tanh_ap(fmaf(0.5f, fmaf(tr0, u0, u0), dxc[mt][pp * 2]));
                    float hn0 = 0.5f * fmaf(tz0, hold0 - c0, hold0 + c0);

                    float tr1 = tanh_ap(d[0][mt][pp * 2 + 1]);
                    float tz1 = tanh_ap(d[1][mt][pp * 2 + 1]);
                    float u1 = d[2][mt][pp * 2 + 1] + e4.z;
                    float c1 = tanh_ap(fmaf(0.5f, fmaf(tr1, u1, u1), dxc[mt][pp * 2 + 1]));
                    float hn1 = 0.5f * fmaf(tz1, hold1 - c1, hold1 + c1);

                    oacc[rr] = fmaf(hn0, e4.y, oacc[rr]);
                    oacc[rr] = fmaf(hn1, e4.w, oacc[rr]);
                    sHf[(2 * w) * 128 + tid] = hn0;
                    sHf[(2 * w + 1) * 128 + tid] = hn1;
                }
            }
        }
        // all MMAs of step t done -> rebuild A fragments from fp32 h (bf16)
#pragma unroll
        for (int mt = 0; mt < 2; mt++)
#pragma unroll
            for (int ks = 0; ks < 4; ks++)
#pragma unroll
                for (int c = 0; c < 4; c++) {
                    int w = (mt * 4 + ks) * 4 + c;
                    Ah[mt][ks][c] = pk2(sHf[(2 * w) * 128 + tid],
                                        sHf[(2 * w + 1) * 128 + tid]);
                }
#pragma unroll
        for (int rr = 0; rr < 4; rr++) {
            float v = oacc[rr];
            v += __shfl_xor_sync(0xffffffffu, v, 1);
            v += __shfl_xor_sync(0xffffffffu, v, 2);
            v = fmaxf(v + bo0, 0.f);
            sSeq[t * 128 + wid * 32 + g4 + rr * 8] = v;  // quad lanes write same value
        }
        // one barrier per step: staging of t+1 complete + reads of buf[t&1] done
        __syncthreads();
    }

    const float* sWp = (const float*)(smem + SM_WP);
    const float* sbp = (const float*)(smem + SM_BP);
    float sq[12];
#pragma unroll
    for (int tt = 0; tt < 12; tt++) sq[tt] = sSeq[tt * 128 + tid];
    float pr[12];
#pragma unroll
    for (int p = 0; p < 12; p++) {
        float a = sbp[p];
#pragma unroll
        for (int tt = 0; tt < 12; tt++) a = fmaf(sq[tt], sWp[p * 12 + tt], a);
        pr[p] = a;
    }
    size_t base = (size_t)(bn0 + tid) * 12;
    float4* o4 = (float4*)(out + base);
    o4[0] = make_float4(pr[0], pr[1], pr[2], pr[3]);
    o4[1] = make_float4(pr[4], pr[5], pr[6], pr[7]);
    o4[2] = make_float4(pr[8], pr[9], pr[10], pr[11]);
    if (dup) {
        float4* d4 = (float4*)(out + NPRED + base);
        d4[0] = make_float4(pr[0], pr[1], pr[2], pr[3]);
        d4[1] = make_float4(pr[4], pr[5], pr[6], pr[7]);
        d4[2] = make_float4(pr[8], pr[9], pr[10], pr[11]);
    }
}

extern "C" void kernel_launch(void* const* d_in, const int* in_sizes, int n_in,
                              void* d_out, int out_size) {
    Meta m;
    m.wz = (const float*)d_in[2];
    m.bz = (const float*)d_in[3];
    for (int g = 0; g < 6; g++) {   // rx, rh, zx, zh, cx, ch
        m.Wl[g] = (const float*)d_in[4 + g * 4];
        m.bl[g] = (const float*)d_in[5 + g * 4];
        m.Wb[g] = (const float*)d_in[6 + g * 4];
        m.bb[g] = (const float*)d_in[7 + g * 4];
    }
    m.Wo = (const float*)d_in[28];
    const float* x  = (const float*)d_in[0];
    const float* bo = (const float*)d_in[29];
    const float* Wp = (const float*)d_in[30];
    const float* bp = (const float*)d_in[31];
    float* out = (float*)d_out;

    pre_kernel<<<364, 256>>>(m);

    int dup = (out_size >= 2 * NPRED) ? 1 : 0;
    cudaFuncSetAttribute(gru_mma, cudaFuncAttributeMaxDynamicSharedMemorySize, SMEM_BYTES);
    gru_mma<<<1024, 128, SMEM_BYTES>>>(x, bo, Wp, bp, out, dup);
}